// round 3
// baseline (speedup 1.0000x reference)
#include <cuda_runtime.h>
#include <cuda_bf16.h>
#include <cstdint>

#define BB    16
#define NPTS  4096
#define MQ    1024
#define KNB   32
#define CFEAT 64
#define S_TOTAL (BB*MQ*KNB)     // 524288
#define FULLM 0xffffffffu

typedef unsigned long long ull;

// ---------------- device scratch (static: no allocations allowed) ----------
__device__ __align__(16) int   g_idx[S_TOTAL];                    // [b][m][k]
__device__ __align__(16) float g_featT[BB*NPTS*CFEAT];            // [b][n][c]
__device__ __align__(16) float g_y1[(size_t)S_TOTAL*64];          // [s][64] pre-BN
__device__ __align__(16) float g_y2[(size_t)S_TOTAL*64];          // [s][64] pre-BN
__device__ __align__(16) float g_y3[(size_t)S_TOTAL*128];         // [s][128] pre-BN
__device__ __align__(16) float g_psum[128*8192];                  // [ch][block]
__device__ __align__(16) float g_psq [128*8192];                  // [ch][block]
__device__ __align__(16) float g_aff[3][256];                     // [stage][a(128)|c(128)]

// ---------------- packed f32x2 helpers -------------------------------------
__device__ __forceinline__ void ffma2(ull &acc, ull ab, ull w2) {
    asm("fma.rn.f32x2 %0, %1, %2, %0;" : "+l"(acc) : "l"(ab), "l"(w2));
}
__device__ __forceinline__ ull pack2(float a, float b) {
    ull r; asm("mov.b64 %0, {%1, %2};" : "=l"(r) : "f"(a), "f"(b)); return r;
}
__device__ __forceinline__ float2 unpack2(ull v) {
    float2 r; asm("mov.b64 {%0, %1}, %2;" : "=f"(r.x), "=f"(r.y) : "l"(v)); return r;
}

// ---------------- features transpose [b][64][n] -> [b][n][64] --------------
__global__ void transpose_feat_kernel(const float* __restrict__ f, float* __restrict__ o)
{
    __shared__ float t[32][33];
    int b = blockIdx.z, n0 = blockIdx.x * 32, c0 = blockIdx.y * 32;
    int x = threadIdx.x, y = threadIdx.y;
#pragma unroll
    for (int i = 0; i < 32; i += 8)
        t[y + i][x] = f[((size_t)b * 64 + (c0 + y + i)) * NPTS + n0 + x];
    __syncthreads();
#pragma unroll
    for (int i = 0; i < 32; i += 8)
        o[((size_t)b * NPTS + n0 + y + i) * 64 + c0 + x] = t[x][y + i];
}

// ---------------- KNN: warp-per-query, sorted 32-list across lanes ---------
__global__ __launch_bounds__(256) void knn_kernel(const float* __restrict__ loc,
                                                  const float* __restrict__ newloc,
                                                  int* __restrict__ idxout)
{
    extern __shared__ float4 sloc[];           // 4096 x {x,y,z,|p|^2} = 64KB
    int b = blockIdx.x >> 4;                   // 16 blocks per batch
    int mgrp = blockIdx.x & 15;                // 64 queries each
    int tid = threadIdx.x;

    for (int i = tid; i < NPTS; i += 256) {
        const float* p = loc + ((size_t)b * NPTS + i) * 3;
        float x = p[0], y = p[1], z = p[2];
        sloc[i] = make_float4(x, y, z, x * x + y * y + z * z);
    }
    __syncthreads();

    int warp = tid >> 5, lane = tid & 31;
    for (int j = 0; j < 8; j++) {
        int m = mgrp * 64 + j * 8 + warp;
        const float* q = newloc + ((size_t)b * MQ + m) * 3;
        float qx = q[0], qy = q[1], qz = q[2];
        float q2 = qx * qx + qy * qy + qz * qz;

        float bv = 3.4e38f;  int bi = 0x7fffffff;   // sorted asc by (v,i) across lanes
        for (int c = 0; c < NPTS / 32; c++) {
            float4 p = sloc[c * 32 + lane];
            float dot = qx * p.x + qy * p.y + qz * p.z;
            float d2 = (q2 + p.w) - 2.0f * dot;
            int   di = c * 32 + lane;
            float tv = __shfl_sync(FULLM, bv, 31);
            int   ti = __shfl_sync(FULLM, bi, 31);
            bool acc = (d2 < tv) || (d2 == tv && di < ti);
            unsigned bm = __ballot_sync(FULLM, acc);
            while (bm) {
                int src = __ffs(bm) - 1; bm &= bm - 1;
                float nv = __shfl_sync(FULLM, d2, src);
                int   ni = c * 32 + src;
                bool lt = (bv < nv) || (bv == nv && bi < ni);
                int pos = __popc(__ballot_sync(FULLM, lt));
                float pv = __shfl_up_sync(FULLM, bv, 1);
                int   pi = __shfl_up_sync(FULLM, bi, 1);
                if (lane == pos)      { bv = nv; bi = ni; }
                else if (lane > pos)  { bv = pv; bi = pi; }
            }
        }
        idxout[((size_t)b * MQ + m) * KNB + lane] = bi;
    }
}

// ---------------- fused gather/affine + GEMM + BN partials -----------------
// MODE 1: build input by gather (stage1, CIN=67). MODE 2: from prev y + affine.
template<int CIN, int COUT, int SPB, int MODE>
__global__ __launch_bounds__(256) void gemm_stage(
    const float* __restrict__ W, const float* __restrict__ src,
    const float* __restrict__ aff, float* __restrict__ yout,
    float* __restrict__ psum, float* __restrict__ psq,
    const int* __restrict__ idx, const float* __restrict__ loc,
    const float* __restrict__ newloc, const float* __restrict__ featT)
{
    constexpr int XS = SPB + 4;       // padded sample stride
    constexpr int WS = COUT + 4;      // padded cout stride
    extern __shared__ float sm[];
    float* Wsm = sm;                  // [CIN][WS]
    float* xT  = sm + CIN * WS;       // [CIN][XS]
    float* afs = xT + CIN * XS;       // [2*CIN] (MODE 2 only)
    int tid = threadIdx.x;
    int sbase = blockIdx.x * SPB;

    for (int i = tid; i < COUT * CIN; i += 256) {
        int co = i / CIN, ci = i - co * CIN;
        Wsm[ci * WS + co] = W[i];
    }
    if (MODE == 2)
        for (int i = tid; i < 2 * CIN; i += 256)
            afs[i] = (i < CIN) ? aff[i] : aff[128 + (i - CIN)];
    __syncthreads();

    if (MODE == 1) {
        int half = tid & 1, sl = tid >> 1;      // SPB==128, 2 threads/sample
        int s = sbase + sl;
        int nidx = idx[s];
        int b = s >> 15;
        const float4* fr = (const float4*)(featT + ((size_t)(b * NPTS + nidx)) * 64 + half * 32);
#pragma unroll
        for (int i = 0; i < 8; i++) {
            float4 v = fr[i];
            int c = 3 + half * 32 + i * 4;
            xT[(c + 0) * XS + sl] = v.x; xT[(c + 1) * XS + sl] = v.y;
            xT[(c + 2) * XS + sl] = v.z; xT[(c + 3) * XS + sl] = v.w;
        }
        if (half == 0) {
            int m = (s >> 5) & (MQ - 1);
            const float* lp = loc + ((size_t)b * NPTS + nidx) * 3;
            const float* qp = newloc + ((size_t)b * MQ + m) * 3;
            xT[0 * XS + sl] = lp[0] - qp[0];
            xT[1 * XS + sl] = lp[1] - qp[1];
            xT[2 * XS + sl] = lp[2] - qp[2];
        }
    } else {
        constexpr int TPS = 256 / SPB;          // threads per sample
        constexpr int CPT = CIN / TPS;          // channels per thread
        int part = tid & (TPS - 1), sl = tid / TPS;
        int s = sbase + sl;
        const float4* fr = (const float4*)(src + (size_t)s * CIN + part * CPT);
#pragma unroll
        for (int i = 0; i < CPT / 4; i++) {
            float4 v = fr[i];
            int c = part * CPT + i * 4;
            v.x = fmaxf(0.f, fmaf(afs[c + 0], v.x, afs[CIN + c + 0]));
            v.y = fmaxf(0.f, fmaf(afs[c + 1], v.y, afs[CIN + c + 1]));
            v.z = fmaxf(0.f, fmaf(afs[c + 2], v.z, afs[CIN + c + 2]));
            v.w = fmaxf(0.f, fmaf(afs[c + 3], v.w, afs[CIN + c + 3]));
            xT[(c + 0) * XS + sl] = v.x; xT[(c + 1) * XS + sl] = v.y;
            xT[(c + 2) * XS + sl] = v.z; xT[(c + 3) * XS + sl] = v.w;
        }
    }
    __syncthreads();

    int trow, tcol;
    if (COUT == 64) { trow = tid >> 5; tcol = tid & 31; }   // 8 x 32
    else           { trow = tid >> 4; tcol = tid & 15; }    // 16 x 16

    ull acc[4][4];                                          // [sample][out-pair]
#pragma unroll
    for (int s = 0; s < 4; s++)
#pragma unroll
        for (int p = 0; p < 4; p++) acc[s][p] = 0ull;

    const float* wrow = Wsm + trow * 8;
    const float* xcol = xT + tcol * 4;
#pragma unroll 4
    for (int ci = 0; ci < CIN; ci++) {
        float4 xv = *(const float4*)(xcol + (size_t)ci * XS);
        ulonglong2 wa = *(const ulonglong2*)(wrow + (size_t)ci * WS);
        ulonglong2 wb = *(const ulonglong2*)(wrow + (size_t)ci * WS + 4);
        ull x0 = pack2(xv.x, xv.x), x1 = pack2(xv.y, xv.y);
        ull x2 = pack2(xv.z, xv.z), x3 = pack2(xv.w, xv.w);
        ffma2(acc[0][0], x0, wa.x); ffma2(acc[0][1], x0, wa.y);
        ffma2(acc[0][2], x0, wb.x); ffma2(acc[0][3], x0, wb.y);
        ffma2(acc[1][0], x1, wa.x); ffma2(acc[1][1], x1, wa.y);
        ffma2(acc[1][2], x1, wb.x); ffma2(acc[1][3], x1, wb.y);
        ffma2(acc[2][0], x2, wa.x); ffma2(acc[2][1], x2, wa.y);
        ffma2(acc[2][2], x2, wb.x); ffma2(acc[2][3], x2, wb.y);
        ffma2(acc[3][0], x3, wa.x); ffma2(acc[3][1], x3, wa.y);
        ffma2(acc[3][2], x3, wb.x); ffma2(acc[3][3], x3, wb.y);
    }

    float ps[8], pq[8];
#pragma unroll
    for (int o = 0; o < 8; o++) { ps[o] = 0.f; pq[o] = 0.f; }
#pragma unroll
    for (int s = 0; s < 4; s++) {
        float v[8];
#pragma unroll
        for (int p = 0; p < 4; p++) {
            float2 f = unpack2(acc[s][p]);
            v[2 * p] = f.x; v[2 * p + 1] = f.y;
        }
        int gs = sbase + tcol * 4 + s;
        float4* yp = (float4*)(yout + (size_t)gs * COUT + trow * 8);
        yp[0] = make_float4(v[0], v[1], v[2], v[3]);
        yp[1] = make_float4(v[4], v[5], v[6], v[7]);
#pragma unroll
        for (int o = 0; o < 8; o++) { ps[o] += v[o]; pq[o] += v[o] * v[o]; }
    }
    constexpr int RW = (COUT == 64) ? 32 : 16;
#pragma unroll
    for (int off = RW / 2; off >= 1; off >>= 1)
#pragma unroll
        for (int o = 0; o < 8; o++) {
            ps[o] += __shfl_xor_sync(FULLM, ps[o], off);
            pq[o] += __shfl_xor_sync(FULLM, pq[o], off);
        }
    if (tcol == 0) {
#pragma unroll
        for (int o = 0; o < 8; o++) {
            int ch = trow * 8 + o;
            psum[(size_t)ch * 8192 + blockIdx.x] = ps[o];
            psq [(size_t)ch * 8192 + blockIdx.x] = pq[o];
        }
    }
}

// ---------------- BN finalize: fold into affine (a, c) ---------------------
__global__ void bn_finalize(const float* __restrict__ psum, const float* __restrict__ psq,
                            const float* __restrict__ g, const float* __restrict__ beta,
                            float* __restrict__ aff, int NB)
{
    int ch = blockIdx.x, tid = threadIdx.x;
    __shared__ float s1[256], s2[256];
    float a = 0.f, q = 0.f;
    for (int i = tid; i < NB; i += 256) {
        a += psum[(size_t)ch * 8192 + i];
        q += psq [(size_t)ch * 8192 + i];
    }
    s1[tid] = a; s2[tid] = q; __syncthreads();
    for (int st = 128; st > 0; st >>= 1) {
        if (tid < st) { s1[tid] += s1[tid + st]; s2[tid] += s2[tid + st]; }
        __syncthreads();
    }
    if (tid == 0) {
        const float invS = 1.0f / (float)S_TOTAL;
        float mu = s1[0] * invS;
        float var = s2[0] * invS - mu * mu;
        float rs = rsqrtf(var + 1e-5f);
        float aa = g[ch] * rs;
        aff[ch] = aa;
        aff[128 + ch] = beta[ch] - mu * aa;
    }
}

// ---------------- affine3 + relu + max over K, transpose to [b][c][m] ------
__global__ __launch_bounds__(256) void maxk_kernel(const float* __restrict__ y3,
                                                   const float* __restrict__ aff,
                                                   float* __restrict__ out)
{
    __shared__ float res[8 * 128];
    int b = blockIdx.x >> 7;
    int m0 = (blockIdx.x & 127) * 8;
    int tid = threadIdx.x;
    int c = tid & 127, mh = tid >> 7;
    float a = aff[c], cc = aff[128 + c];
#pragma unroll
    for (int r = 0; r < 4; r++) {
        int ml = mh * 4 + r;
        int m = m0 + ml;
        const float* yp = y3 + ((size_t)((b * MQ + m) * KNB)) * 128 + c;
        float mx = -3.4e38f;
#pragma unroll 8
        for (int k = 0; k < KNB; k++)
            mx = fmaxf(mx, fmaf(a, yp[(size_t)k * 128], cc));
        res[ml * 128 + c] = fmaxf(0.f, mx);
    }
    __syncthreads();
    for (int i = tid; i < 1024; i += 256) {
        int ch = i >> 3, j = i & 7;
        out[((size_t)b * 128 + ch) * MQ + m0 + j] = res[j * 128 + ch];
    }
}

// ---------------- launch ----------------------------------------------------
extern "C" void kernel_launch(void* const* d_in, const int* in_sizes, int n_in,
                              void* d_out, int out_size)
{
    const float* loc    = (const float*)d_in[0];
    const float* newloc = (const float*)d_in[1];
    const float* feats  = (const float*)d_in[2];
    const float* W1 = (const float*)d_in[3];
    const float* g1 = (const float*)d_in[4];
    const float* b1 = (const float*)d_in[5];
    const float* W2 = (const float*)d_in[6];
    const float* g2 = (const float*)d_in[7];
    const float* b2 = (const float*)d_in[8];
    const float* W3 = (const float*)d_in[9];
    const float* g3 = (const float*)d_in[10];
    const float* b3 = (const float*)d_in[11];
    float* out = (float*)d_out;

    int*   idx   = nullptr;  cudaGetSymbolAddress((void**)&idx,   g_idx);
    float* featT = nullptr;  cudaGetSymbolAddress((void**)&featT, g_featT);
    float* y1    = nullptr;  cudaGetSymbolAddress((void**)&y1,    g_y1);
    float* y2    = nullptr;  cudaGetSymbolAddress((void**)&y2,    g_y2);
    float* y3    = nullptr;  cudaGetSymbolAddress((void**)&y3,    g_y3);
    float* psum  = nullptr;  cudaGetSymbolAddress((void**)&psum,  g_psum);
    float* psq   = nullptr;  cudaGetSymbolAddress((void**)&psq,   g_psq);
    float* aff   = nullptr;  cudaGetSymbolAddress((void**)&aff,   g_aff);

    // opt-in dynamic smem > 48KB (idempotent; executes eagerly, not captured)
    cudaFuncSetAttribute(knn_kernel, cudaFuncAttributeMaxDynamicSharedMemorySize, 65536);
    cudaFuncSetAttribute(gemm_stage<67, 64, 128, 1>, cudaFuncAttributeMaxDynamicSharedMemorySize, 53600);
    cudaFuncSetAttribute(gemm_stage<64, 64, 128, 2>, cudaFuncAttributeMaxDynamicSharedMemorySize, 51712);
    cudaFuncSetAttribute(gemm_stage<64, 128, 64, 2>, cudaFuncAttributeMaxDynamicSharedMemorySize, 51712);

    transpose_feat_kernel<<<dim3(NPTS / 32, 2, BB), dim3(32, 8)>>>(feats, featT);
    knn_kernel<<<256, 256, 65536>>>(loc, newloc, idx);

    gemm_stage<67, 64, 128, 1><<<4096, 256, 53600>>>(
        W1, nullptr, nullptr, y1, psum, psq, idx, loc, newloc, featT);
    bn_finalize<<<64, 256>>>(psum, psq, g1, b1, aff + 0 * 256, 4096);

    gemm_stage<64, 64, 128, 2><<<4096, 256, 51712>>>(
        W2, y1, aff + 0 * 256, y2, psum, psq, idx, loc, newloc, featT);
    bn_finalize<<<64, 256>>>(psum, psq, g2, b2, aff + 1 * 256, 4096);

    gemm_stage<64, 128, 64, 2><<<8192, 256, 51712>>>(
        W3, y2, aff + 1 * 256, y3, psum, psq, idx, loc, newloc, featT);
    bn_finalize<<<128, 256>>>(psum, psq, g3, b3, aff + 2 * 256, 8192);

    maxk_kernel<<<BB * 128, 256>>>(y3, aff + 2 * 256, out);
    (void)in_sizes; (void)n_in; (void)out_size;
}

// round 4
// speedup vs baseline: 1.1866x; 1.1866x over previous
#include <cuda_runtime.h>
#include <cuda_bf16.h>
#include <cstdint>

#define BB    16
#define NPTS  4096
#define MQ    1024
#define KNB   32
#define CFEAT 64
#define S_TOTAL (BB*MQ*KNB)     // 524288
#define FULLM 0xffffffffu

typedef unsigned long long ull;

// ---------------- device scratch (static: no allocations allowed) ----------
__device__ __align__(16) int   g_idx[S_TOTAL];                    // [b][m][k]
__device__ __align__(16) float g_featT[BB*NPTS*CFEAT];            // [b][n][c]
__device__ __align__(16) float g_y1[(size_t)S_TOTAL*64];          // [s][64] pre-BN
__device__ __align__(16) float g_y2[(size_t)S_TOTAL*64];          // [s][64] pre-BN
__device__ __align__(16) float g_ymax[BB*MQ*128];                 // [bm][128]
__device__ __align__(16) float g_ymin[BB*MQ*128];                 // [bm][128]
__device__ __align__(16) float g_psum[128*8192];                  // [ch][block]
__device__ __align__(16) float g_psq [128*8192];                  // [ch][block]
__device__ __align__(16) float g_aff[3][256];                     // [stage][a(128)|c(128)]

// ---------------- packed f32x2 helpers -------------------------------------
__device__ __forceinline__ void ffma2(ull &acc, ull ab, ull w2) {
    asm("fma.rn.f32x2 %0, %1, %2, %0;" : "+l"(acc) : "l"(ab), "l"(w2));
}
__device__ __forceinline__ ull pack2(float a, float b) {
    ull r; asm("mov.b64 %0, {%1, %2};" : "=l"(r) : "f"(a), "f"(b)); return r;
}
__device__ __forceinline__ float2 unpack2(ull v) {
    float2 r; asm("mov.b64 {%0, %1}, %2;" : "=f"(r.x), "=f"(r.y) : "l"(v)); return r;
}

// ---------------- KNN + features transpose fused ---------------------------
// grid 512: 32 blocks per batch. Each block:
//  phase A: transpose its 128-n slice of features [64][4096] -> [n][64]
//  phase B: load all loc into SoA smem
//  phase C: 8 warps x 4 queries, sorted-32 insertion across lanes
__global__ __launch_bounds__(256) void knnT_kernel(const float* __restrict__ loc,
                                                   const float* __restrict__ newloc,
                                                   const float* __restrict__ feats,
                                                   float* __restrict__ featT,
                                                   int* __restrict__ idxout)
{
    extern __shared__ float smem[];            // 12288 floats = 48KB
    int b = blockIdx.x >> 5;
    int grp = blockIdx.x & 31;
    int tid = threadIdx.x;

    // Phase A: transpose slice n in [grp*128, grp*128+128)
    {
        int n0 = grp * 128;
        for (int i = tid; i < 64 * 128; i += 256) {
            int c = i >> 7, n = i & 127;
            smem[n * 65 + c] = feats[((size_t)b * 64 + c) * NPTS + n0 + n];
        }
        __syncthreads();
        for (int i = tid; i < 64 * 128; i += 256) {
            int n = i >> 6, c = i & 63;
            featT[((size_t)b * NPTS + n0 + n) * 64 + c] = smem[n * 65 + c];
        }
        __syncthreads();
    }

    // Phase B: SoA loc
    float* sx = smem;
    float* sy = smem + NPTS;
    float* sz = smem + 2 * NPTS;
    for (int i = tid; i < NPTS; i += 256) {
        const float* p = loc + ((size_t)b * NPTS + i) * 3;
        sx[i] = p[0]; sy[i] = p[1]; sz[i] = p[2];
    }
    __syncthreads();

    // Phase C
    int warp = tid >> 5, lane = tid & 31;
    for (int j = 0; j < 4; j++) {
        int m = grp * 32 + j * 8 + warp;
        const float* q = newloc + ((size_t)b * MQ + m) * 3;
        float qx = q[0], qy = q[1], qz = q[2];
        float q2 = qx * qx + qy * qy + qz * qz;

        float bv = 3.4e38f;  int bi = 0x7fffffff;   // sorted asc by (v,i) across lanes
        for (int cg = 0; cg < NPTS / 128; cg++) {
            float tv = __shfl_sync(FULLM, bv, 31);
            int   ti = __shfl_sync(FULLM, bi, 31);
            float d2v[4];
#pragma unroll
            for (int u = 0; u < 4; u++) {
                int p = (cg * 4 + u) * 32 + lane;
                float x = sx[p], y = sy[p], z = sz[p];
                float w = x * x + y * y + z * z;
                float dot = qx * x + qy * y + qz * z;
                d2v[u] = (q2 + w) - 2.0f * dot;
            }
#pragma unroll
            for (int u = 0; u < 4; u++) {
                int di = (cg * 4 + u) * 32 + lane;
                bool acc = (d2v[u] < tv) || (d2v[u] == tv && di < ti);
                unsigned bm = __ballot_sync(FULLM, acc);
                if (!bm) continue;
                while (bm) {
                    int src = __ffs(bm) - 1; bm &= bm - 1;
                    float nv = __shfl_sync(FULLM, d2v[u], src);
                    int   ni = (cg * 4 + u) * 32 + src;
                    bool lt = (bv < nv) || (bv == nv && bi < ni);
                    int pos = __popc(__ballot_sync(FULLM, lt));
                    float pv = __shfl_up_sync(FULLM, bv, 1);
                    int   pi = __shfl_up_sync(FULLM, bi, 1);
                    if (lane == pos)      { bv = nv; bi = ni; }
                    else if (lane > pos)  { bv = pv; bi = pi; }
                }
                tv = __shfl_sync(FULLM, bv, 31);
                ti = __shfl_sync(FULLM, bi, 31);
            }
        }
        idxout[((size_t)b * MQ + m) * KNB + lane] = bi;
    }
}

// ---------------- fused gather/affine + GEMM + BN partials -----------------
// MODE 1: build input by gather (stage1, CIN=67). MODE 2: from prev y + affine.
// RED 1: don't store y; store per-(m,ch) max and min over k instead.
template<int CIN, int COUT, int SPB, int MODE, int RED>
__global__ __launch_bounds__(256) void gemm_stage(
    const float* __restrict__ W, const float* __restrict__ src,
    const float* __restrict__ aff, float* __restrict__ yout,
    float* __restrict__ ymax, float* __restrict__ ymin,
    float* __restrict__ psum, float* __restrict__ psq,
    const int* __restrict__ idx, const float* __restrict__ loc,
    const float* __restrict__ newloc, const float* __restrict__ featT)
{
    constexpr int XS = SPB + 4;       // padded sample stride
    constexpr int WS = COUT + 4;      // padded cout stride
    extern __shared__ float sm[];
    float* Wsm = sm;                  // [CIN][WS]
    float* xT  = sm + CIN * WS;       // [CIN][XS]
    float* afs = xT + CIN * XS;       // [2*CIN] (MODE 2 only)
    int tid = threadIdx.x;
    int sbase = blockIdx.x * SPB;

    for (int i = tid; i < COUT * CIN; i += 256) {
        int co = i / CIN, ci = i - co * CIN;
        Wsm[ci * WS + co] = W[i];
    }
    if (MODE == 2)
        for (int i = tid; i < 2 * CIN; i += 256)
            afs[i] = (i < CIN) ? aff[i] : aff[128 + (i - CIN)];
    __syncthreads();

    if (MODE == 1) {
        int half = tid & 1, sl = tid >> 1;      // SPB==128, 2 threads/sample
        int s = sbase + sl;
        int nidx = idx[s];
        int b = s >> 15;
        const float4* fr = (const float4*)(featT + ((size_t)(b * NPTS + nidx)) * 64 + half * 32);
#pragma unroll
        for (int i = 0; i < 8; i++) {
            float4 v = fr[i];
            int c = 3 + half * 32 + i * 4;
            xT[(c + 0) * XS + sl] = v.x; xT[(c + 1) * XS + sl] = v.y;
            xT[(c + 2) * XS + sl] = v.z; xT[(c + 3) * XS + sl] = v.w;
        }
        if (half == 0) {
            int m = (s >> 5) & (MQ - 1);
            const float* lp = loc + ((size_t)b * NPTS + nidx) * 3;
            const float* qp = newloc + ((size_t)b * MQ + m) * 3;
            xT[0 * XS + sl] = lp[0] - qp[0];
            xT[1 * XS + sl] = lp[1] - qp[1];
            xT[2 * XS + sl] = lp[2] - qp[2];
        }
    } else {
        constexpr int TPS = 256 / SPB;          // threads per sample
        constexpr int CPT = CIN / TPS;          // channels per thread
        int part = tid & (TPS - 1), sl = tid / TPS;
        int s = sbase + sl;
        const float4* fr = (const float4*)(src + (size_t)s * CIN + part * CPT);
#pragma unroll
        for (int i = 0; i < CPT / 4; i++) {
            float4 v = fr[i];
            int c = part * CPT + i * 4;
            v.x = fmaxf(0.f, fmaf(afs[c + 0], v.x, afs[CIN + c + 0]));
            v.y = fmaxf(0.f, fmaf(afs[c + 1], v.y, afs[CIN + c + 1]));
            v.z = fmaxf(0.f, fmaf(afs[c + 2], v.z, afs[CIN + c + 2]));
            v.w = fmaxf(0.f, fmaf(afs[c + 3], v.w, afs[CIN + c + 3]));
            xT[(c + 0) * XS + sl] = v.x; xT[(c + 1) * XS + sl] = v.y;
            xT[(c + 2) * XS + sl] = v.z; xT[(c + 3) * XS + sl] = v.w;
        }
    }
    __syncthreads();

    int trow, tcol;
    if (COUT == 64) { trow = tid >> 5; tcol = tid & 31; }   // 8 x 32
    else           { trow = tid >> 4; tcol = tid & 15; }    // 16 x 16

    ull acc[4][4];                                          // [sample][out-pair]
#pragma unroll
    for (int s = 0; s < 4; s++)
#pragma unroll
        for (int p = 0; p < 4; p++) acc[s][p] = 0ull;

    const float* wrow = Wsm + trow * 8;
    const float* xcol = xT + tcol * 4;
#pragma unroll 4
    for (int ci = 0; ci < CIN; ci++) {
        float4 xv = *(const float4*)(xcol + (size_t)ci * XS);
        ulonglong2 wa = *(const ulonglong2*)(wrow + (size_t)ci * WS);
        ulonglong2 wb = *(const ulonglong2*)(wrow + (size_t)ci * WS + 4);
        ull x0 = pack2(xv.x, xv.x), x1 = pack2(xv.y, xv.y);
        ull x2 = pack2(xv.z, xv.z), x3 = pack2(xv.w, xv.w);
        ffma2(acc[0][0], x0, wa.x); ffma2(acc[0][1], x0, wa.y);
        ffma2(acc[0][2], x0, wb.x); ffma2(acc[0][3], x0, wb.y);
        ffma2(acc[1][0], x1, wa.x); ffma2(acc[1][1], x1, wa.y);
        ffma2(acc[1][2], x1, wb.x); ffma2(acc[1][3], x1, wb.y);
        ffma2(acc[2][0], x2, wa.x); ffma2(acc[2][1], x2, wa.y);
        ffma2(acc[2][2], x2, wb.x); ffma2(acc[2][3], x2, wb.y);
        ffma2(acc[3][0], x3, wa.x); ffma2(acc[3][1], x3, wa.y);
        ffma2(acc[3][2], x3, wb.x); ffma2(acc[3][3], x3, wb.y);
    }

    float ps[8], pq[8], vmax[8], vmin[8];
#pragma unroll
    for (int o = 0; o < 8; o++) {
        ps[o] = 0.f; pq[o] = 0.f; vmax[o] = -3.4e38f; vmin[o] = 3.4e38f;
    }
#pragma unroll
    for (int s = 0; s < 4; s++) {
        float v[8];
#pragma unroll
        for (int p = 0; p < 4; p++) {
            float2 f = unpack2(acc[s][p]);
            v[2 * p] = f.x; v[2 * p + 1] = f.y;
        }
        if (!RED) {
            int gs = sbase + tcol * 4 + s;
            float4* yp = (float4*)(yout + (size_t)gs * COUT + trow * 8);
            yp[0] = make_float4(v[0], v[1], v[2], v[3]);
            yp[1] = make_float4(v[4], v[5], v[6], v[7]);
        }
#pragma unroll
        for (int o = 0; o < 8; o++) {
            ps[o] += v[o]; pq[o] += v[o] * v[o];
            if (RED) { vmax[o] = fmaxf(vmax[o], v[o]); vmin[o] = fminf(vmin[o], v[o]); }
        }
    }
    constexpr int RW = (COUT == 64) ? 32 : 16;
#pragma unroll
    for (int off = RW / 2; off >= 1; off >>= 1)
#pragma unroll
        for (int o = 0; o < 8; o++) {
            ps[o] += __shfl_xor_sync(FULLM, ps[o], off);
            pq[o] += __shfl_xor_sync(FULLM, pq[o], off);
        }
    if (tcol == 0) {
#pragma unroll
        for (int o = 0; o < 8; o++) {
            int ch = trow * 8 + o;
            psum[(size_t)ch * 8192 + blockIdx.x] = ps[o];
            psq [(size_t)ch * 8192 + blockIdx.x] = pq[o];
        }
    }
    if (RED) {
        // k-reduction: samples of one m live in tcol groups of 8 (SPB=64, m=gs>>5)
#pragma unroll
        for (int off = 1; off <= 4; off <<= 1)
#pragma unroll
            for (int o = 0; o < 8; o++) {
                vmax[o] = fmaxf(vmax[o], __shfl_xor_sync(FULLM, vmax[o], off));
                vmin[o] = fminf(vmin[o], __shfl_xor_sync(FULLM, vmin[o], off));
            }
        if ((tcol & 7) == 0) {
            int mglob = (sbase >> 5) + (tcol >> 3);
            float4* mp = (float4*)(ymax + (size_t)mglob * 128 + trow * 8);
            float4* np = (float4*)(ymin + (size_t)mglob * 128 + trow * 8);
            mp[0] = make_float4(vmax[0], vmax[1], vmax[2], vmax[3]);
            mp[1] = make_float4(vmax[4], vmax[5], vmax[6], vmax[7]);
            np[0] = make_float4(vmin[0], vmin[1], vmin[2], vmin[3]);
            np[1] = make_float4(vmin[4], vmin[5], vmin[6], vmin[7]);
        }
    }
}

// ---------------- BN finalize: fold into affine (a, c) ---------------------
__global__ void bn_finalize(const float* __restrict__ psum, const float* __restrict__ psq,
                            const float* __restrict__ g, const float* __restrict__ beta,
                            float* __restrict__ aff, int NB)
{
    int ch = blockIdx.x, tid = threadIdx.x;
    __shared__ float s1[256], s2[256];
    float a = 0.f, q = 0.f;
    for (int i = tid; i < NB; i += 256) {
        a += psum[(size_t)ch * 8192 + i];
        q += psq [(size_t)ch * 8192 + i];
    }
    s1[tid] = a; s2[tid] = q; __syncthreads();
    for (int st = 128; st > 0; st >>= 1) {
        if (tid < st) { s1[tid] += s1[tid + st]; s2[tid] += s2[tid + st]; }
        __syncthreads();
    }
    if (tid == 0) {
        const float invS = 1.0f / (float)S_TOTAL;
        float mu = s1[0] * invS;
        float var = s2[0] * invS - mu * mu;
        float rs = rsqrtf(var + 1e-5f);
        float aa = g[ch] * rs;
        aff[ch] = aa;
        aff[128 + ch] = beta[ch] - mu * aa;
    }
}

// ---------------- final: affine3 + relu on k-extremum, transpose -----------
__global__ __launch_bounds__(256) void final_kernel(const float* __restrict__ ymax,
                                                    const float* __restrict__ ymin,
                                                    const float* __restrict__ aff,
                                                    float* __restrict__ out)
{
    __shared__ float t[128 * 65];
    int b = blockIdx.x >> 4;
    int mg = blockIdx.x & 15;          // 64 queries per block
    int tid = threadIdx.x;
    for (int i = tid; i < 8192; i += 256) {
        int m = i >> 7, ch = i & 127;
        float a = aff[ch], cc = aff[128 + ch];
        size_t base = ((size_t)(b * MQ + mg * 64 + m)) * 128 + ch;
        float val = (a > 0.f) ? ymax[base] : ymin[base];
        t[ch * 65 + m] = fmaxf(0.f, fmaf(a, val, cc));
    }
    __syncthreads();
    for (int i = tid; i < 8192; i += 256) {
        int ch = i >> 6, m = i & 63;
        out[((size_t)(b * 128 + ch)) * MQ + mg * 64 + m] = t[ch * 65 + m];
    }
}

// ---------------- launch ----------------------------------------------------
extern "C" void kernel_launch(void* const* d_in, const int* in_sizes, int n_in,
                              void* d_out, int out_size)
{
    const float* loc    = (const float*)d_in[0];
    const float* newloc = (const float*)d_in[1];
    const float* feats  = (const float*)d_in[2];
    const float* W1 = (const float*)d_in[3];
    const float* g1 = (const float*)d_in[4];
    const float* b1 = (const float*)d_in[5];
    const float* W2 = (const float*)d_in[6];
    const float* g2 = (const float*)d_in[7];
    const float* b2 = (const float*)d_in[8];
    const float* W3 = (const float*)d_in[9];
    const float* g3 = (const float*)d_in[10];
    const float* b3 = (const float*)d_in[11];
    float* out = (float*)d_out;

    int*   idx   = nullptr;  cudaGetSymbolAddress((void**)&idx,   g_idx);
    float* featT = nullptr;  cudaGetSymbolAddress((void**)&featT, g_featT);
    float* y1    = nullptr;  cudaGetSymbolAddress((void**)&y1,    g_y1);
    float* y2    = nullptr;  cudaGetSymbolAddress((void**)&y2,    g_y2);
    float* ymax  = nullptr;  cudaGetSymbolAddress((void**)&ymax,  g_ymax);
    float* ymin  = nullptr;  cudaGetSymbolAddress((void**)&ymin,  g_ymin);
    float* psum  = nullptr;  cudaGetSymbolAddress((void**)&psum,  g_psum);
    float* psq   = nullptr;  cudaGetSymbolAddress((void**)&psq,   g_psq);
    float* aff   = nullptr;  cudaGetSymbolAddress((void**)&aff,   g_aff);

    // opt-in dynamic smem > 48KB (idempotent; executes eagerly, not captured)
    cudaFuncSetAttribute(knnT_kernel, cudaFuncAttributeMaxDynamicSharedMemorySize, 49152);
    cudaFuncSetAttribute(gemm_stage<67, 64, 128, 1, 0>, cudaFuncAttributeMaxDynamicSharedMemorySize, 53600);
    cudaFuncSetAttribute(gemm_stage<64, 64, 128, 2, 0>, cudaFuncAttributeMaxDynamicSharedMemorySize, 51712);
    cudaFuncSetAttribute(gemm_stage<64, 128, 64, 2, 1>, cudaFuncAttributeMaxDynamicSharedMemorySize, 51712);

    // launch #0: knn + feature transpose
    knnT_kernel<<<512, 256, 49152>>>(loc, newloc, feats, featT, idx);

    // launch #1,#2
    gemm_stage<67, 64, 128, 1, 0><<<4096, 256, 53600>>>(
        W1, nullptr, nullptr, y1, nullptr, nullptr, psum, psq, idx, loc, newloc, featT);
    bn_finalize<<<64, 256>>>(psum, psq, g1, b1, aff + 0 * 256, 4096);

    // launch #3,#4
    gemm_stage<64, 64, 128, 2, 0><<<4096, 256, 51712>>>(
        W2, y1, aff + 0 * 256, y2, nullptr, nullptr, psum, psq, idx, loc, newloc, featT);
    bn_finalize<<<64, 256>>>(psum, psq, g2, b2, aff + 1 * 256, 4096);

    // launch #5 (ncu capture target): gemm3 with fused k-max/min, no y3
    gemm_stage<64, 128, 64, 2, 1><<<8192, 256, 51712>>>(
        W3, y2, aff + 1 * 256, nullptr, ymax, ymin, psum, psq, idx, loc, newloc, featT);
    bn_finalize<<<128, 256>>>(psum, psq, g3, b3, aff + 2 * 256, 8192);

    // launch #7: tiny epilogue
    final_kernel<<<BB * 16, 256>>>(ymax, ymin, aff + 2 * 256, out);
    (void)in_sizes; (void)n_in; (void)out_size;
}

// round 5
// speedup vs baseline: 1.1871x; 1.0004x over previous
#include <cuda_runtime.h>
#include <cuda_bf16.h>
#include <cstdint>

#define BB    16
#define NPTS  4096
#define MQ    1024
#define KNB   32
#define CFEAT 64
#define S_TOTAL (BB*MQ*KNB)     // 524288
#define FULLM 0xffffffffu

typedef unsigned long long ull;

// ---------------- device scratch (static: no allocations allowed) ----------
__device__ __align__(16) int   g_idx[S_TOTAL];                    // [b][m][k]
__device__ __align__(16) float g_featT[BB*NPTS*CFEAT];            // [b][n][c]
__device__ __align__(16) float g_y1[(size_t)S_TOTAL*64];          // [s][64] pre-BN
__device__ __align__(16) float g_y2[(size_t)S_TOTAL*64];          // [s][64] pre-BN
__device__ __align__(16) float g_ymax[BB*MQ*128];                 // [bm][128]
__device__ __align__(16) float g_ymin[BB*MQ*128];                 // [bm][128]
__device__ __align__(16) float g_psum[128*8192];                  // [ch][block]
__device__ __align__(16) float g_psq [128*8192];                  // [ch][block]
__device__ __align__(16) float g_aff[3][256];                     // [stage][a(128)|c(128)]

// ---------------- packed f32x2 helpers -------------------------------------
__device__ __forceinline__ void ffma2(ull &acc, ull ab, ull w2) {
    asm("fma.rn.f32x2 %0, %1, %2, %0;" : "+l"(acc) : "l"(ab), "l"(w2));
}
__device__ __forceinline__ ull pack2(float a, float b) {
    ull r; asm("mov.b64 %0, {%1, %2};" : "=l"(r) : "f"(a), "f"(b)); return r;
}
__device__ __forceinline__ float2 unpack2(ull v) {
    float2 r; asm("mov.b64 {%0, %1}, %2;" : "=f"(r.x), "=f"(r.y) : "l"(v)); return r;
}

// ---------------- KNN + features transpose fused ---------------------------
__global__ __launch_bounds__(256) void knnT_kernel(const float* __restrict__ loc,
                                                   const float* __restrict__ newloc,
                                                   const float* __restrict__ feats,
                                                   float* __restrict__ featT,
                                                   int* __restrict__ idxout)
{
    extern __shared__ float smem[];            // 12288 floats = 48KB
    int b = blockIdx.x >> 5;
    int grp = blockIdx.x & 31;
    int tid = threadIdx.x;

    // Phase A: transpose slice n in [grp*128, grp*128+128)
    {
        int n0 = grp * 128;
        for (int i = tid; i < 64 * 128; i += 256) {
            int c = i >> 7, n = i & 127;
            smem[n * 65 + c] = feats[((size_t)b * 64 + c) * NPTS + n0 + n];
        }
        __syncthreads();
        for (int i = tid; i < 64 * 128; i += 256) {
            int n = i >> 6, c = i & 63;
            featT[((size_t)b * NPTS + n0 + n) * 64 + c] = smem[n * 65 + c];
        }
        __syncthreads();
    }

    // Phase B: SoA loc
    float* sx = smem;
    float* sy = smem + NPTS;
    float* sz = smem + 2 * NPTS;
    for (int i = tid; i < NPTS; i += 256) {
        const float* p = loc + ((size_t)b * NPTS + i) * 3;
        sx[i] = p[0]; sy[i] = p[1]; sz[i] = p[2];
    }
    __syncthreads();

    // Phase C
    int warp = tid >> 5, lane = tid & 31;
    for (int j = 0; j < 4; j++) {
        int m = grp * 32 + j * 8 + warp;
        const float* q = newloc + ((size_t)b * MQ + m) * 3;
        float qx = q[0], qy = q[1], qz = q[2];
        float q2 = qx * qx + qy * qy + qz * qz;

        float bv = 3.4e38f;  int bi = 0x7fffffff;   // sorted asc by (v,i) across lanes
        for (int cg = 0; cg < NPTS / 128; cg++) {
            float tv = __shfl_sync(FULLM, bv, 31);
            int   ti = __shfl_sync(FULLM, bi, 31);
            float d2v[4];
#pragma unroll
            for (int u = 0; u < 4; u++) {
                int p = (cg * 4 + u) * 32 + lane;
                float x = sx[p], y = sy[p], z = sz[p];
                float w = x * x + y * y + z * z;
                float dot = qx * x + qy * y + qz * z;
                d2v[u] = (q2 + w) - 2.0f * dot;
            }
#pragma unroll
            for (int u = 0; u < 4; u++) {
                int di = (cg * 4 + u) * 32 + lane;
                bool acc = (d2v[u] < tv) || (d2v[u] == tv && di < ti);
                unsigned bm = __ballot_sync(FULLM, acc);
                if (!bm) continue;
                while (bm) {
                    int src = __ffs(bm) - 1; bm &= bm - 1;
                    float nv = __shfl_sync(FULLM, d2v[u], src);
                    int   ni = (cg * 4 + u) * 32 + src;
                    bool lt = (bv < nv) || (bv == nv && bi < ni);
                    int pos = __popc(__ballot_sync(FULLM, lt));
                    float pv = __shfl_up_sync(FULLM, bv, 1);
                    int   pi = __shfl_up_sync(FULLM, bi, 1);
                    if (lane == pos)      { bv = nv; bi = ni; }
                    else if (lane > pos)  { bv = pv; bi = pi; }
                }
                tv = __shfl_sync(FULLM, bv, 31);
                ti = __shfl_sync(FULLM, bi, 31);
            }
        }
        idxout[((size_t)b * MQ + m) * KNB + lane] = bi;
    }
}

// ---------------- fused gather/affine + GEMM + BN partials -----------------
// 128 threads; each thread computes an 8x8 register tile (8 couts x 8 samples).
// MODE 1: build input by gather (stage1, CIN=67). MODE 2: from prev y + affine.
// RED 1: don't store y; store per-(m,ch) max and min over k instead.
template<int CIN, int COUT, int SPB, int MODE, int RED>
__global__ __launch_bounds__(128, 4) void gemm_stage(
    const float* __restrict__ W, const float* __restrict__ src,
    const float* __restrict__ aff, float* __restrict__ yout,
    float* __restrict__ ymax, float* __restrict__ ymin,
    float* __restrict__ psum, float* __restrict__ psq,
    const int* __restrict__ idx, const float* __restrict__ loc,
    const float* __restrict__ newloc, const float* __restrict__ featT)
{
    constexpr int XS = SPB + 4;       // padded sample stride
    constexpr int WS = COUT + 4;      // padded cout stride
    extern __shared__ float sm[];
    float* Wsm = sm;                  // [CIN][WS]
    float* xT  = sm + CIN * WS;       // [CIN][XS]
    float* afs = xT + CIN * XS;       // [2*CIN] (MODE 2 only)
    int tid = threadIdx.x;
    int sbase = blockIdx.x * SPB;

    for (int i = tid; i < COUT * CIN; i += 128) {
        int co = i / CIN, ci = i - co * CIN;
        Wsm[ci * WS + co] = W[i];
    }
    if (MODE == 2)
        for (int i = tid; i < 2 * CIN; i += 128)
            afs[i] = (i < CIN) ? aff[i] : aff[128 + (i - CIN)];

    if (MODE == 1) {
        // SPB == 128: one thread per sample
        int sl = tid;
        int s = sbase + sl;
        int nidx = idx[s];
        int b = s >> 15;
        const float4* fr = (const float4*)(featT + ((size_t)(b * NPTS + nidx)) * 64);
#pragma unroll
        for (int i = 0; i < 16; i++) {
            float4 v = fr[i];
            int c = 3 + i * 4;
            xT[(c + 0) * XS + sl] = v.x; xT[(c + 1) * XS + sl] = v.y;
            xT[(c + 2) * XS + sl] = v.z; xT[(c + 3) * XS + sl] = v.w;
        }
        {
            int m = (s >> 5) & (MQ - 1);
            const float* lp = loc + ((size_t)b * NPTS + nidx) * 3;
            const float* qp = newloc + ((size_t)b * MQ + m) * 3;
            xT[0 * XS + sl] = lp[0] - qp[0];
            xT[1 * XS + sl] = lp[1] - qp[1];
            xT[2 * XS + sl] = lp[2] - qp[2];
        }
    } else {
        constexpr int TPS = 128 / SPB;          // threads per sample (1 or 2)
        constexpr int CPT = CIN / TPS;          // channels per thread
        int part = tid & (TPS - 1), sl = tid / TPS;
        int s = sbase + sl;
        const float4* fr = (const float4*)(src + (size_t)s * CIN + part * CPT);
        __syncthreads();   // afs ready before use
#pragma unroll
        for (int i = 0; i < CPT / 4; i++) {
            float4 v = fr[i];
            int c = part * CPT + i * 4;
            v.x = fmaxf(0.f, fmaf(afs[c + 0], v.x, afs[CIN + c + 0]));
            v.y = fmaxf(0.f, fmaf(afs[c + 1], v.y, afs[CIN + c + 1]));
            v.z = fmaxf(0.f, fmaf(afs[c + 2], v.z, afs[CIN + c + 2]));
            v.w = fmaxf(0.f, fmaf(afs[c + 3], v.w, afs[CIN + c + 3]));
            xT[(c + 0) * XS + sl] = v.x; xT[(c + 1) * XS + sl] = v.y;
            xT[(c + 2) * XS + sl] = v.z; xT[(c + 3) * XS + sl] = v.w;
        }
    }
    __syncthreads();

    int trow, tcol;
    if (COUT == 64) { trow = tid >> 4; tcol = tid & 15; }   // 8 x 16, SPB=128
    else            { trow = tid >> 3; tcol = tid & 7;  }   // 16 x 8, SPB=64

    ull acc[8][4];                                          // [sample][out-pair]
#pragma unroll
    for (int s = 0; s < 8; s++)
#pragma unroll
        for (int p = 0; p < 4; p++) acc[s][p] = 0ull;

    const float* wrow = Wsm + trow * 8;
    const float* xcol = xT + tcol * 8;
#pragma unroll 2
    for (int ci = 0; ci < CIN; ci++) {
        float4 xa = *(const float4*)(xcol + (size_t)ci * XS);
        float4 xb = *(const float4*)(xcol + (size_t)ci * XS + 4);
        ulonglong2 wa = *(const ulonglong2*)(wrow + (size_t)ci * WS);
        ulonglong2 wb = *(const ulonglong2*)(wrow + (size_t)ci * WS + 4);
        ull xp[8];
        xp[0] = pack2(xa.x, xa.x); xp[1] = pack2(xa.y, xa.y);
        xp[2] = pack2(xa.z, xa.z); xp[3] = pack2(xa.w, xa.w);
        xp[4] = pack2(xb.x, xb.x); xp[5] = pack2(xb.y, xb.y);
        xp[6] = pack2(xb.z, xb.z); xp[7] = pack2(xb.w, xb.w);
#pragma unroll
        for (int s = 0; s < 8; s++) {
            ffma2(acc[s][0], xp[s], wa.x);
            ffma2(acc[s][1], xp[s], wa.y);
            ffma2(acc[s][2], xp[s], wb.x);
            ffma2(acc[s][3], xp[s], wb.y);
        }
    }

    float ps[8], pq[8], vmax[8], vmin[8];
#pragma unroll
    for (int o = 0; o < 8; o++) {
        ps[o] = 0.f; pq[o] = 0.f; vmax[o] = -3.4e38f; vmin[o] = 3.4e38f;
    }
#pragma unroll
    for (int s = 0; s < 8; s++) {
        float v[8];
#pragma unroll
        for (int p = 0; p < 4; p++) {
            float2 f = unpack2(acc[s][p]);
            v[2 * p] = f.x; v[2 * p + 1] = f.y;
        }
        if (!RED) {
            int gs = sbase + tcol * 8 + s;
            float4* yp = (float4*)(yout + (size_t)gs * COUT + trow * 8);
            yp[0] = make_float4(v[0], v[1], v[2], v[3]);
            yp[1] = make_float4(v[4], v[5], v[6], v[7]);
        }
#pragma unroll
        for (int o = 0; o < 8; o++) {
            ps[o] += v[o]; pq[o] += v[o] * v[o];
            if (RED) { vmax[o] = fmaxf(vmax[o], v[o]); vmin[o] = fminf(vmin[o], v[o]); }
        }
    }
    constexpr int RW = (COUT == 64) ? 16 : 8;   // lanes per trow group
#pragma unroll
    for (int off = RW / 2; off >= 1; off >>= 1)
#pragma unroll
        for (int o = 0; o < 8; o++) {
            ps[o] += __shfl_xor_sync(FULLM, ps[o], off);
            pq[o] += __shfl_xor_sync(FULLM, pq[o], off);
        }
    if (tcol == 0) {
#pragma unroll
        for (int o = 0; o < 8; o++) {
            int ch = trow * 8 + o;
            psum[(size_t)ch * 8192 + blockIdx.x] = ps[o];
            psq [(size_t)ch * 8192 + blockIdx.x] = pq[o];
        }
    }
    if (RED) {
        // SPB=64: samples tcol*8..+7; m0 = tcol 0..3, m1 = tcol 4..7
#pragma unroll
        for (int off = 1; off <= 2; off <<= 1)
#pragma unroll
            for (int o = 0; o < 8; o++) {
                vmax[o] = fmaxf(vmax[o], __shfl_xor_sync(FULLM, vmax[o], off));
                vmin[o] = fminf(vmin[o], __shfl_xor_sync(FULLM, vmin[o], off));
            }
        if ((tcol & 3) == 0) {
            int mglob = (sbase >> 5) + (tcol >> 2);
            float4* mp = (float4*)(ymax + (size_t)mglob * 128 + trow * 8);
            float4* np = (float4*)(ymin + (size_t)mglob * 128 + trow * 8);
            mp[0] = make_float4(vmax[0], vmax[1], vmax[2], vmax[3]);
            mp[1] = make_float4(vmax[4], vmax[5], vmax[6], vmax[7]);
            np[0] = make_float4(vmin[0], vmin[1], vmin[2], vmin[3]);
            np[1] = make_float4(vmin[4], vmin[5], vmin[6], vmin[7]);
        }
    }
}

// ---------------- BN finalize: fold into affine (a, c) ---------------------
__global__ void bn_finalize(const float* __restrict__ psum, const float* __restrict__ psq,
                            const float* __restrict__ g, const float* __restrict__ beta,
                            float* __restrict__ aff, int NB)
{
    int ch = blockIdx.x, tid = threadIdx.x;
    __shared__ float s1[256], s2[256];
    float a = 0.f, q = 0.f;
    for (int i = tid; i < NB; i += 256) {
        a += psum[(size_t)ch * 8192 + i];
        q += psq [(size_t)ch * 8192 + i];
    }
    s1[tid] = a; s2[tid] = q; __syncthreads();
    for (int st = 128; st > 0; st >>= 1) {
        if (tid < st) { s1[tid] += s1[tid + st]; s2[tid] += s2[tid + st]; }
        __syncthreads();
    }
    if (tid == 0) {
        const float invS = 1.0f / (float)S_TOTAL;
        float mu = s1[0] * invS;
        float var = s2[0] * invS - mu * mu;
        float rs = rsqrtf(var + 1e-5f);
        float aa = g[ch] * rs;
        aff[ch] = aa;
        aff[128 + ch] = beta[ch] - mu * aa;
    }
}

// ---------------- final: affine3 + relu on k-extremum, transpose -----------
__global__ __launch_bounds__(256) void final_kernel(const float* __restrict__ ymax,
                                                    const float* __restrict__ ymin,
                                                    const float* __restrict__ aff,
                                                    float* __restrict__ out)
{
    __shared__ float t[128 * 65];
    int b = blockIdx.x >> 4;
    int mg = blockIdx.x & 15;          // 64 queries per block
    int tid = threadIdx.x;
    for (int i = tid; i < 8192; i += 256) {
        int m = i >> 7, ch = i & 127;
        float a = aff[ch], cc = aff[128 + ch];
        size_t base = ((size_t)(b * MQ + mg * 64 + m)) * 128 + ch;
        float val = (a > 0.f) ? ymax[base] : ymin[base];
        t[ch * 65 + m] = fmaxf(0.f, fmaf(a, val, cc));
    }
    __syncthreads();
    for (int i = tid; i < 8192; i += 256) {
        int ch = i >> 6, m = i & 63;
        out[((size_t)(b * 128 + ch)) * MQ + mg * 64 + m] = t[ch * 65 + m];
    }
}

// ---------------- launch ----------------------------------------------------
extern "C" void kernel_launch(void* const* d_in, const int* in_sizes, int n_in,
                              void* d_out, int out_size)
{
    const float* loc    = (const float*)d_in[0];
    const float* newloc = (const float*)d_in[1];
    const float* feats  = (const float*)d_in[2];
    const float* W1 = (const float*)d_in[3];
    const float* g1 = (const float*)d_in[4];
    const float* b1 = (const float*)d_in[5];
    const float* W2 = (const float*)d_in[6];
    const float* g2 = (const float*)d_in[7];
    const float* b2 = (const float*)d_in[8];
    const float* W3 = (const float*)d_in[9];
    const float* g3 = (const float*)d_in[10];
    const float* b3 = (const float*)d_in[11];
    float* out = (float*)d_out;

    int*   idx   = nullptr;  cudaGetSymbolAddress((void**)&idx,   g_idx);
    float* featT = nullptr;  cudaGetSymbolAddress((void**)&featT, g_featT);
    float* y1    = nullptr;  cudaGetSymbolAddress((void**)&y1,    g_y1);
    float* y2    = nullptr;  cudaGetSymbolAddress((void**)&y2,    g_y2);
    float* ymax  = nullptr;  cudaGetSymbolAddress((void**)&ymax,  g_ymax);
    float* ymin  = nullptr;  cudaGetSymbolAddress((void**)&ymin,  g_ymin);
    float* psum  = nullptr;  cudaGetSymbolAddress((void**)&psum,  g_psum);
    float* psq   = nullptr;  cudaGetSymbolAddress((void**)&psq,   g_psq);
    float* aff   = nullptr;  cudaGetSymbolAddress((void**)&aff,   g_aff);

    // opt-in dynamic smem > 48KB (idempotent; executes eagerly, not captured)
    cudaFuncSetAttribute(knnT_kernel, cudaFuncAttributeMaxDynamicSharedMemorySize, 49152);
    cudaFuncSetAttribute(gemm_stage<67, 64, 128, 1, 0>, cudaFuncAttributeMaxDynamicSharedMemorySize, 53600);
    cudaFuncSetAttribute(gemm_stage<64, 64, 128, 2, 0>, cudaFuncAttributeMaxDynamicSharedMemorySize, 51712);
    cudaFuncSetAttribute(gemm_stage<64, 128, 64, 2, 1>, cudaFuncAttributeMaxDynamicSharedMemorySize, 51712);

    // launch #0: knn + feature transpose
    knnT_kernel<<<512, 256, 49152>>>(loc, newloc, feats, featT, idx);

    // launch #1,#2
    gemm_stage<67, 64, 128, 1, 0><<<4096, 128, 53600>>>(
        W1, nullptr, nullptr, y1, nullptr, nullptr, psum, psq, idx, loc, newloc, featT);
    bn_finalize<<<64, 256>>>(psum, psq, g1, b1, aff + 0 * 256, 4096);

    // launch #3,#4
    gemm_stage<64, 64, 128, 2, 0><<<4096, 128, 51712>>>(
        W2, y1, aff + 0 * 256, y2, nullptr, nullptr, psum, psq, idx, loc, newloc, featT);
    bn_finalize<<<64, 256>>>(psum, psq, g2, b2, aff + 1 * 256, 4096);

    // launch #5: gemm3 with fused k-max/min, no y3
    gemm_stage<64, 128, 64, 2, 1><<<8192, 128, 51712>>>(
        W3, y2, aff + 1 * 256, nullptr, ymax, ymin, psum, psq, idx, loc, newloc, featT);
    bn_finalize<<<128, 256>>>(psum, psq, g3, b3, aff + 2 * 256, 8192);

    // launch #7: tiny epilogue
    final_kernel<<<BB * 16, 256>>>(ymax, ymin, aff + 2 * 256, out);
    (void)in_sizes; (void)n_in; (void)out_size;
}

// round 8
// speedup vs baseline: 1.1875x; 1.0004x over previous
#include <cuda_runtime.h>
#include <cuda_bf16.h>
#include <cstdint>

#define BB    16
#define NPTS  4096
#define MQ    1024
#define KNB   32
#define CFEAT 64
#define S_TOTAL (BB*MQ*KNB)     // 524288
#define FULLM 0xffffffffu

typedef unsigned long long ull;

// ---------------- device scratch (static: no allocations allowed) ----------
__device__ __align__(16) int   g_idx[S_TOTAL];                    // [b][m][k]
__device__ __align__(16) float g_featT[BB*NPTS*CFEAT];            // [b][n][c]
__device__ __align__(16) float g_y1[(size_t)S_TOTAL*64];          // [s][64] pre-BN
__device__ __align__(16) float g_y2[(size_t)S_TOTAL*64];          // [s][64] pre-BN
__device__ __align__(16) float g_ymax[BB*MQ*128];                 // [bm][128]
__device__ __align__(16) float g_ymin[BB*MQ*128];                 // [bm][128]
__device__ __align__(16) float g_psum[128*8192];                  // [ch][block]
__device__ __align__(16) float g_psq [128*8192];                  // [ch][block]
__device__ __align__(16) float g_aff[3][256];                     // [stage][a(128)|c(128)]

// ---------------- packed f32x2 helpers -------------------------------------
__device__ __forceinline__ void ffma2(ull &acc, ull ab, ull w2) {
    asm("fma.rn.f32x2 %0, %1, %2, %0;" : "+l"(acc) : "l"(ab), "l"(w2));
}
__device__ __forceinline__ ull pack2(float a, float b) {
    ull r; asm("mov.b64 %0, {%1, %2};" : "=l"(r) : "f"(a), "f"(b)); return r;
}
__device__ __forceinline__ float2 unpack2(ull v) {
    float2 r; asm("mov.b64 {%0, %1}, %2;" : "=f"(r.x), "=f"(r.y) : "l"(v)); return r;
}

// ---------------- KNN + features transpose fused ---------------------------
__global__ __launch_bounds__(256) void knnT_kernel(const float* __restrict__ loc,
                                                   const float* __restrict__ newloc,
                                                   const float* __restrict__ feats,
                                                   float* __restrict__ featT,
                                                   int* __restrict__ idxout)
{
    extern __shared__ float smem[];            // 12288 floats = 48KB
    int b = blockIdx.x >> 5;
    int grp = blockIdx.x & 31;
    int tid = threadIdx.x;

    // Phase A: transpose slice n in [grp*128, grp*128+128)
    {
        int n0 = grp * 128;
        for (int i = tid; i < 64 * 128; i += 256) {
            int c = i >> 7, n = i & 127;
            smem[n * 65 + c] = feats[((size_t)b * 64 + c) * NPTS + n0 + n];
        }
        __syncthreads();
        for (int i = tid; i < 64 * 128; i += 256) {
            int n = i >> 6, c = i & 63;
            featT[((size_t)b * NPTS + n0 + n) * 64 + c] = smem[n * 65 + c];
        }
        __syncthreads();
    }

    // Phase B: SoA loc
    float* sx = smem;
    float* sy = smem + NPTS;
    float* sz = smem + 2 * NPTS;
    for (int i = tid; i < NPTS; i += 256) {
        const float* p = loc + ((size_t)b * NPTS + i) * 3;
        sx[i] = p[0]; sy[i] = p[1]; sz[i] = p[2];
    }
    __syncthreads();

    // Phase C
    int warp = tid >> 5, lane = tid & 31;
    for (int j = 0; j < 4; j++) {
        int m = grp * 32 + j * 8 + warp;
        const float* q = newloc + ((size_t)b * MQ + m) * 3;
        float qx = q[0], qy = q[1], qz = q[2];
        float q2 = qx * qx + qy * qy + qz * qz;

        float bv = 3.4e38f;  int bi = 0x7fffffff;   // sorted asc by (v,i) across lanes
        for (int cg = 0; cg < NPTS / 128; cg++) {
            float tv = __shfl_sync(FULLM, bv, 31);
            int   ti = __shfl_sync(FULLM, bi, 31);
            float d2v[4];
#pragma unroll
            for (int u = 0; u < 4; u++) {
                int p = (cg * 4 + u) * 32 + lane;
                float x = sx[p], y = sy[p], z = sz[p];
                float w = x * x + y * y + z * z;
                float dot = qx * x + qy * y + qz * z;
                d2v[u] = (q2 + w) - 2.0f * dot;
            }
#pragma unroll
            for (int u = 0; u < 4; u++) {
                int di = (cg * 4 + u) * 32 + lane;
                bool acc = (d2v[u] < tv) || (d2v[u] == tv && di < ti);
                unsigned bm = __ballot_sync(FULLM, acc);
                if (!bm) continue;
                while (bm) {
                    int src = __ffs(bm) - 1; bm &= bm - 1;
                    float nv = __shfl_sync(FULLM, d2v[u], src);
                    int   ni = (cg * 4 + u) * 32 + src;
                    bool lt = (bv < nv) || (bv == nv && bi < ni);
                    int pos = __popc(__ballot_sync(FULLM, lt));
                    float pv = __shfl_up_sync(FULLM, bv, 1);
                    int   pi = __shfl_up_sync(FULLM, bi, 1);
                    if (lane == pos)      { bv = nv; bi = ni; }
                    else if (lane > pos)  { bv = pv; bi = pi; }
                }
                tv = __shfl_sync(FULLM, bv, 31);
                ti = __shfl_sync(FULLM, bi, 31);
            }
        }
        idxout[((size_t)b * MQ + m) * KNB + lane] = bi;
    }
}

// ---------------- fused gather/affine + GEMM + BN partials -----------------
// 128 threads; each thread computes an 8x8 register tile (8 couts x 8 samples).
// MODE 1: build input by gather (stage1, CIN=67). MODE 2: from prev y + affine.
// RED 1: don't store y; store per-(m,ch) max and min over k instead.
template<int CIN, int COUT, int SPB, int MODE, int RED>
__global__ __launch_bounds__(128, 4) void gemm_stage(
    const float* __restrict__ W, const float* __restrict__ src,
    const float* __restrict__ aff, float* __restrict__ yout,
    float* __restrict__ ymax, float* __restrict__ ymin,
    float* __restrict__ psum, float* __restrict__ psq,
    const int* __restrict__ idx, const float* __restrict__ loc,
    const float* __restrict__ newloc, const float* __restrict__ featT)
{
    constexpr int XS = SPB + 4;       // padded sample stride
    constexpr int WS = COUT + 4;      // padded cout stride
    extern __shared__ float sm[];
    float* Wsm = sm;                  // [CIN][WS]
    float* xT  = sm + CIN * WS;       // [CIN][XS]
    float* afs = xT + CIN * XS;       // [2*CIN] (MODE 2 only)
    int tid = threadIdx.x;
    int sbase = blockIdx.x * SPB;

    for (int i = tid; i < COUT * CIN; i += 128) {
        int co = i / CIN, ci = i - co * CIN;
        Wsm[ci * WS + co] = W[i];
    }
    if (MODE == 2)
        for (int i = tid; i < 2 * CIN; i += 128)
            afs[i] = (i < CIN) ? aff[i] : aff[128 + (i - CIN)];

    if (MODE == 1) {
        // SPB == 128: one thread per sample
        int sl = tid;
        int s = sbase + sl;
        int nidx = idx[s];
        int b = s >> 15;
        const float4* fr = (const float4*)(featT + ((size_t)(b * NPTS + nidx)) * 64);
#pragma unroll
        for (int i = 0; i < 16; i++) {
            float4 v = fr[i];
            int c = 3 + i * 4;
            xT[(c + 0) * XS + sl] = v.x; xT[(c + 1) * XS + sl] = v.y;
            xT[(c + 2) * XS + sl] = v.z; xT[(c + 3) * XS + sl] = v.w;
        }
        {
            int m = (s >> 5) & (MQ - 1);
            const float* lp = loc + ((size_t)b * NPTS + nidx) * 3;
            const float* qp = newloc + ((size_t)b * MQ + m) * 3;
            xT[0 * XS + sl] = lp[0] - qp[0];
            xT[1 * XS + sl] = lp[1] - qp[1];
            xT[2 * XS + sl] = lp[2] - qp[2];
        }
    } else {
        constexpr int TPS = 128 / SPB;          // threads per sample (1 or 2)
        constexpr int CPT = CIN / TPS;          // channels per thread
        int part = tid & (TPS - 1), sl = tid / TPS;
        int s = sbase + sl;
        const float4* fr = (const float4*)(src + (size_t)s * CIN + part * CPT);
        __syncthreads();   // afs ready before use
#pragma unroll
        for (int i = 0; i < CPT / 4; i++) {
            float4 v = fr[i];
            int c = part * CPT + i * 4;
            v.x = fmaxf(0.f, fmaf(afs[c + 0], v.x, afs[CIN + c + 0]));
            v.y = fmaxf(0.f, fmaf(afs[c + 1], v.y, afs[CIN + c + 1]));
            v.z = fmaxf(0.f, fmaf(afs[c + 2], v.z, afs[CIN + c + 2]));
            v.w = fmaxf(0.f, fmaf(afs[c + 3], v.w, afs[CIN + c + 3]));
            xT[(c + 0) * XS + sl] = v.x; xT[(c + 1) * XS + sl] = v.y;
            xT[(c + 2) * XS + sl] = v.z; xT[(c + 3) * XS + sl] = v.w;
        }
    }
    __syncthreads();

    int trow, tcol;
    if (COUT == 64) { trow = tid >> 4; tcol = tid & 15; }   // 8 x 16, SPB=128
    else            { trow = tid >> 3; tcol = tid & 7;  }   // 16 x 8, SPB=64

    ull acc[8][4];                                          // [sample][out-pair]
#pragma unroll
    for (int s = 0; s < 8; s++)
#pragma unroll
        for (int p = 0; p < 4; p++) acc[s][p] = 0ull;

    const float* wrow = Wsm + trow * 8;
    const float* xcol = xT + tcol * 8;
#pragma unroll 2
    for (int ci = 0; ci < CIN; ci++) {
        float4 xa = *(const float4*)(xcol + (size_t)ci * XS);
        float4 xb = *(const float4*)(xcol + (size_t)ci * XS + 4);
        ulonglong2 wa = *(const ulonglong2*)(wrow + (size_t)ci * WS);
        ulonglong2 wb = *(const ulonglong2*)(wrow + (size_t)ci * WS + 4);
        ull xp[8];
        xp[0] = pack2(xa.x, xa.x); xp[1] = pack2(xa.y, xa.y);
        xp[2] = pack2(xa.z, xa.z); xp[3] = pack2(xa.w, xa.w);
        xp[4] = pack2(xb.x, xb.x); xp[5] = pack2(xb.y, xb.y);
        xp[6] = pack2(xb.z, xb.z); xp[7] = pack2(xb.w, xb.w);
#pragma unroll
        for (int s = 0; s < 8; s++) {
            ffma2(acc[s][0], xp[s], wa.x);
            ffma2(acc[s][1], xp[s], wa.y);
            ffma2(acc[s][2], xp[s], wb.x);
            ffma2(acc[s][3], xp[s], wb.y);
        }
    }

    float ps[8], pq[8], vmax[8], vmin[8];
#pragma unroll
    for (int o = 0; o < 8; o++) {
        ps[o] = 0.f; pq[o] = 0.f; vmax[o] = -3.4e38f; vmin[o] = 3.4e38f;
    }
#pragma unroll
    for (int s = 0; s < 8; s++) {
        float v[8];
#pragma unroll
        for (int p = 0; p < 4; p++) {
            float2 f = unpack2(acc[s][p]);
            v[2 * p] = f.x; v[2 * p + 1] = f.y;
        }
        if (!RED) {
            int gs = sbase + tcol * 8 + s;
            float4* yp = (float4*)(yout + (size_t)gs * COUT + trow * 8);
            yp[0] = make_float4(v[0], v[1], v[2], v[3]);
            yp[1] = make_float4(v[4], v[5], v[6], v[7]);
        }
#pragma unroll
        for (int o = 0; o < 8; o++) {
            ps[o] += v[o]; pq[o] += v[o] * v[o];
            if (RED) { vmax[o] = fmaxf(vmax[o], v[o]); vmin[o] = fminf(vmin[o], v[o]); }
        }
    }
    constexpr int RW = (COUT == 64) ? 16 : 8;   // lanes per trow group
#pragma unroll
    for (int off = RW / 2; off >= 1; off >>= 1)
#pragma unroll
        for (int o = 0; o < 8; o++) {
            ps[o] += __shfl_xor_sync(FULLM, ps[o], off);
            pq[o] += __shfl_xor_sync(FULLM, pq[o], off);
        }
    if (tcol == 0) {
#pragma unroll
        for (int o = 0; o < 8; o++) {
            int ch = trow * 8 + o;
            psum[(size_t)ch * 8192 + blockIdx.x] = ps[o];
            psq [(size_t)ch * 8192 + blockIdx.x] = pq[o];
        }
    }
    if (RED) {
        // SPB=64: samples tcol*8..+7; m0 = tcol 0..3, m1 = tcol 4..7
#pragma unroll
        for (int off = 1; off <= 2; off <<= 1)
#pragma unroll
            for (int o = 0; o < 8; o++) {
                vmax[o] = fmaxf(vmax[o], __shfl_xor_sync(FULLM, vmax[o], off));
                vmin[o] = fminf(vmin[o], __shfl_xor_sync(FULLM, vmin[o], off));
            }
        if ((tcol & 3) == 0) {
            int mglob = (sbase >> 5) + (tcol >> 2);
            float4* mp = (float4*)(ymax + (size_t)mglob * 128 + trow * 8);
            float4* np = (float4*)(ymin + (size_t)mglob * 128 + trow * 8);
            mp[0] = make_float4(vmax[0], vmax[1], vmax[2], vmax[3]);
            mp[1] = make_float4(vmax[4], vmax[5], vmax[6], vmax[7]);
            np[0] = make_float4(vmin[0], vmin[1], vmin[2], vmin[3]);
            np[1] = make_float4(vmin[4], vmin[5], vmin[6], vmin[7]);
        }
    }
}

// ---------------- BN finalize: fold into affine (a, c) ---------------------
__global__ void bn_finalize(const float* __restrict__ psum, const float* __restrict__ psq,
                            const float* __restrict__ g, const float* __restrict__ beta,
                            float* __restrict__ aff, int NB)
{
    int ch = blockIdx.x, tid = threadIdx.x;
    __shared__ float s1[256], s2[256];
    float a = 0.f, q = 0.f;
    for (int i = tid; i < NB; i += 256) {
        a += psum[(size_t)ch * 8192 + i];
        q += psq [(size_t)ch * 8192 + i];
    }
    s1[tid] = a; s2[tid] = q; __syncthreads();
    for (int st = 128; st > 0; st >>= 1) {
        if (tid < st) { s1[tid] += s1[tid + st]; s2[tid] += s2[tid + st]; }
        __syncthreads();
    }
    if (tid == 0) {
        const float invS = 1.0f / (float)S_TOTAL;
        float mu = s1[0] * invS;
        float var = s2[0] * invS - mu * mu;
        float rs = rsqrtf(var + 1e-5f);
        float aa = g[ch] * rs;
        aff[ch] = aa;
        aff[128 + ch] = beta[ch] - mu * aa;
    }
}

// ---------------- final: affine3 + relu on k-extremum, transpose -----------
__global__ __launch_bounds__(256) void final_kernel(const float* __restrict__ ymax,
                                                    const float* __restrict__ ymin,
                                                    const float* __restrict__ aff,
                                                    float* __restrict__ out)
{
    __shared__ float t[128 * 65];
    int b = blockIdx.x >> 4;
    int mg = blockIdx.x & 15;          // 64 queries per block
    int tid = threadIdx.x;
    for (int i = tid; i < 8192; i += 256) {
        int m = i >> 7, ch = i & 127;
        float a = aff[ch], cc = aff[128 + ch];
        size_t base = ((size_t)(b * MQ + mg * 64 + m)) * 128 + ch;
        float val = (a > 0.f) ? ymax[base] : ymin[base];
        t[ch * 65 + m] = fmaxf(0.f, fmaf(a, val, cc));
    }
    __syncthreads();
    for (int i = tid; i < 8192; i += 256) {
        int ch = i >> 6, m = i & 63;
        out[((size_t)(b * 128 + ch)) * MQ + mg * 64 + m] = t[ch * 65 + m];
    }
}

// ---------------- launch ----------------------------------------------------
extern "C" void kernel_launch(void* const* d_in, const int* in_sizes, int n_in,
                              void* d_out, int out_size)
{
    const float* loc    = (const float*)d_in[0];
    const float* newloc = (const float*)d_in[1];
    const float* feats  = (const float*)d_in[2];
    const float* W1 = (const float*)d_in[3];
    const float* g1 = (const float*)d_in[4];
    const float* b1 = (const float*)d_in[5];
    const float* W2 = (const float*)d_in[6];
    const float* g2 = (const float*)d_in[7];
    const float* b2 = (const float*)d_in[8];
    const float* W3 = (const float*)d_in[9];
    const float* g3 = (const float*)d_in[10];
    const float* b3 = (const float*)d_in[11];
    float* out = (float*)d_out;

    int*   idx   = nullptr;  cudaGetSymbolAddress((void**)&idx,   g_idx);
    float* featT = nullptr;  cudaGetSymbolAddress((void**)&featT, g_featT);
    float* y1    = nullptr;  cudaGetSymbolAddress((void**)&y1,    g_y1);
    float* y2    = nullptr;  cudaGetSymbolAddress((void**)&y2,    g_y2);
    float* ymax  = nullptr;  cudaGetSymbolAddress((void**)&ymax,  g_ymax);
    float* ymin  = nullptr;  cudaGetSymbolAddress((void**)&ymin,  g_ymin);
    float* psum  = nullptr;  cudaGetSymbolAddress((void**)&psum,  g_psum);
    float* psq   = nullptr;  cudaGetSymbolAddress((void**)&psq,   g_psq);
    float* aff   = nullptr;  cudaGetSymbolAddress((void**)&aff,   g_aff);

    // opt-in dynamic smem > 48KB (idempotent; executes eagerly, not captured)
    cudaFuncSetAttribute(knnT_kernel, cudaFuncAttributeMaxDynamicSharedMemorySize, 49152);
    cudaFuncSetAttribute(gemm_stage<67, 64, 128, 1, 0>, cudaFuncAttributeMaxDynamicSharedMemorySize, 53600);
    cudaFuncSetAttribute(gemm_stage<64, 64, 128, 2, 0>, cudaFuncAttributeMaxDynamicSharedMemorySize, 51712);
    cudaFuncSetAttribute(gemm_stage<64, 128, 64, 2, 1>, cudaFuncAttributeMaxDynamicSharedMemorySize, 51712);

    // launch #0: knn + feature transpose
    knnT_kernel<<<512, 256, 49152>>>(loc, newloc, feats, featT, idx);

    // launch #1,#2
    gemm_stage<67, 64, 128, 1, 0><<<4096, 128, 53600>>>(
        W1, nullptr, nullptr, y1, nullptr, nullptr, psum, psq, idx, loc, newloc, featT);
    bn_finalize<<<64, 256>>>(psum, psq, g1, b1, aff + 0 * 256, 4096);

    // launch #3,#4
    gemm_stage<64, 64, 128, 2, 0><<<4096, 128, 51712>>>(
        W2, y1, aff + 0 * 256, y2, nullptr, nullptr, psum, psq, idx, loc, newloc, featT);
    bn_finalize<<<64, 256>>>(psum, psq, g2, b2, aff + 1 * 256, 4096);

    // launch #5: gemm3 with fused k-max/min, no y3
    gemm_stage<64, 128, 64, 2, 1><<<8192, 128, 51712>>>(
        W3, y2, aff + 1 * 256, nullptr, ymax, ymin, psum, psq, idx, loc, newloc, featT);
    bn_finalize<<<128, 256>>>(psum, psq, g3, b3, aff + 2 * 256, 8192);

    // launch #7: tiny epilogue
    final_kernel<<<BB * 16, 256>>>(ymax, ymin, aff + 2 * 256, out);
    (void)in_sizes; (void)n_in; (void)out_size;
}

// round 11
// speedup vs baseline: 1.4728x; 1.2402x over previous
#include <cuda_runtime.h>
#include <cuda_bf16.h>
#include <cstdint>

#define BB    16
#define NPTS  4096
#define MQ    1024
#define KNB   32
#define S_TOTAL (BB*MQ*KNB)
#define FULLM 0xffffffffu

// ---------------- device scratch -------------------------------------------
__device__ __align__(16) int   g_idx[S_TOTAL];
__device__ __align__(16) float g_featT[BB*NPTS*64];
__device__ __align__(16) float g_y1[(size_t)S_TOTAL*64];
__device__ __align__(16) float g_y2[(size_t)S_TOTAL*64];
__device__ __align__(16) float g_ymax[BB*MQ*128];
__device__ __align__(16) float g_ymin[BB*MQ*128];
__device__ __align__(16) float g_psum[128*8192];
__device__ __align__(16) float g_psq [128*8192];
__device__ __align__(16) float g_aff[3][256];

// ---------------- mma helpers ----------------------------------------------
__device__ __forceinline__ void ldm4(uint32_t* r, uint32_t addr) {
    asm volatile("ldmatrix.sync.aligned.m8n8.x4.shared.b16 {%0,%1,%2,%3}, [%4];"
        : "=r"(r[0]), "=r"(r[1]), "=r"(r[2]), "=r"(r[3]) : "r"(addr));
}
__device__ __forceinline__ void mma_bf16(float* d, const uint32_t* a,
                                         uint32_t b0, uint32_t b1) {
    asm volatile("mma.sync.aligned.m16n8k16.row.col.f32.bf16.bf16.f32 "
        "{%0,%1,%2,%3}, {%4,%5,%6,%7}, {%8,%9}, {%0,%1,%2,%3};"
        : "+f"(d[0]), "+f"(d[1]), "+f"(d[2]), "+f"(d[3])
        : "r"(a[0]), "r"(a[1]), "r"(a[2]), "r"(a[3]), "r"(b0), "r"(b1));
}
__device__ __forceinline__ void splitStore(__nv_bfloat16* H, __nv_bfloat16* L,
                                           int off, float a, float b) {
    __nv_bfloat162 h = __floats2bfloat162_rn(a, b);
    *(__nv_bfloat162*)(H + off) = h;
    *(__nv_bfloat162*)(L + off) =
        __floats2bfloat162_rn(a - __low2float(h), b - __high2float(h));
}

// ---------------- KNN + features transpose fused ---------------------------
__global__ __launch_bounds__(256) void knnT_kernel(const float* __restrict__ loc,
                                                   const float* __restrict__ newloc,
                                                   const float* __restrict__ feats,
                                                   float* __restrict__ featT,
                                                   int* __restrict__ idxout)
{
    extern __shared__ float smem[];
    int b = blockIdx.x >> 5;
    int grp = blockIdx.x & 31;
    int tid = threadIdx.x;
    {
        int n0 = grp * 128;
        for (int i = tid; i < 64 * 128; i += 256) {
            int c = i >> 7, n = i & 127;
            smem[n * 65 + c] = feats[((size_t)b * 64 + c) * NPTS + n0 + n];
        }
        __syncthreads();
        for (int i = tid; i < 64 * 128; i += 256) {
            int n = i >> 6, c = i & 63;
            featT[((size_t)b * NPTS + n0 + n) * 64 + c] = smem[n * 65 + c];
        }
        __syncthreads();
    }
    float* sx = smem; float* sy = smem + NPTS; float* sz = smem + 2 * NPTS;
    for (int i = tid; i < NPTS; i += 256) {
        const float* p = loc + ((size_t)b * NPTS + i) * 3;
        sx[i] = p[0]; sy[i] = p[1]; sz[i] = p[2];
    }
    __syncthreads();
    int warp = tid >> 5, lane = tid & 31;
    for (int j = 0; j < 4; j++) {
        int m = grp * 32 + j * 8 + warp;
        const float* q = newloc + ((size_t)b * MQ + m) * 3;
        float qx = q[0], qy = q[1], qz = q[2];
        float q2 = qx * qx + qy * qy + qz * qz;
        float bv = 3.4e38f;  int bi = 0x7fffffff;
        for (int cg = 0; cg < NPTS / 128; cg++) {
            float tv = __shfl_sync(FULLM, bv, 31);
            int   ti = __shfl_sync(FULLM, bi, 31);
            float d2v[4];
#pragma unroll
            for (int u = 0; u < 4; u++) {
                int p = (cg * 4 + u) * 32 + lane;
                float x = sx[p], y = sy[p], z = sz[p];
                float w = x * x + y * y + z * z;
                d2v[u] = (q2 + w) - 2.0f * (qx * x + qy * y + qz * z);
            }
#pragma unroll
            for (int u = 0; u < 4; u++) {
                int di = (cg * 4 + u) * 32 + lane;
                bool acc = (d2v[u] < tv) || (d2v[u] == tv && di < ti);
                unsigned bm = __ballot_sync(FULLM, acc);
                if (!bm) continue;
                while (bm) {
                    int src = __ffs(bm) - 1; bm &= bm - 1;
                    float nv = __shfl_sync(FULLM, d2v[u], src);
                    int   ni = (cg * 4 + u) * 32 + src;
                    bool lt = (bv < nv) || (bv == nv && bi < ni);
                    int pos = __popc(__ballot_sync(FULLM, lt));
                    float pv = __shfl_up_sync(FULLM, bv, 1);
                    int   pi = __shfl_up_sync(FULLM, bi, 1);
                    if (lane == pos)      { bv = nv; bi = ni; }
                    else if (lane > pos)  { bv = pv; bi = pi; }
                }
                tv = __shfl_sync(FULLM, bv, 31);
                ti = __shfl_sync(FULLM, bi, 31);
            }
        }
        idxout[((size_t)b * MQ + m) * KNB + lane] = bi;
    }
}

// ---------------- tensor-core GEMM stage (bf16x3 emulation) ----------------
// STAGE 1: gather input, COUT=64, 128 samp/CTA, loc channels in fp32 acc-init.
// STAGE 2: affine+relu(y1), COUT=64, 128 samp/CTA.
// STAGE 3: affine+relu(y2), COUT=128, 64 samp/CTA, fused k-max/min, no y out.
template<int STAGE>
__global__ __launch_bounds__(128) void gemm_mma(
    const float* __restrict__ W, const float* __restrict__ src,
    const float* __restrict__ aff, float* __restrict__ yout,
    float* __restrict__ ymax, float* __restrict__ ymin,
    float* __restrict__ psum, float* __restrict__ psq,
    const int* __restrict__ idx, const float* __restrict__ loc,
    const float* __restrict__ newloc, const float* __restrict__ featT)
{
    constexpr int COUT = (STAGE == 3) ? 128 : 64;
    constexpr int SPB  = (STAGE == 3) ? 64 : 128;
    constexpr int NT   = COUT / 8;          // 8 or 16 n-tiles
    constexpr int MT   = SPB / 64;          // 2 or 1 m-tiles per warp
    constexpr int ABYT = SPB * 72 * 2;
    constexpr int WBYT = COUT * 72 * 2;

    extern __shared__ __align__(16) char smc[];
    __nv_bfloat16* Ah = (__nv_bfloat16*)smc;
    __nv_bfloat16* Al = (__nv_bfloat16*)(smc + ABYT);
    __nv_bfloat16* Wh = (__nv_bfloat16*)(smc + 2 * ABYT);
    __nv_bfloat16* Wl = (__nv_bfloat16*)(smc + 2 * ABYT + WBYT);
    float* afs  = (float*)(smc + 2 * ABYT + 2 * WBYT);   // 128
    float* sloc = afs + 128;                              // 128*4
    float* wloc = sloc + 512;                             // 64*4
    float* sps  = wloc + 256;                             // 4*COUT
    float* spq  = sps + 4 * COUT;                         // 4*COUT
    float* smx  = spq + 4 * COUT;                         // 4*COUT (stage3)
    float* smn  = smx + 4 * COUT;

    int tid = threadIdx.x, warp = tid >> 5, lane = tid & 31;
    int blk = blockIdx.x;
    int sbase = blk * SPB;

    if (STAGE > 1 && tid < 128)
        afs[tid] = (tid < 64) ? aff[tid] : aff[128 + tid - 64];
    __syncthreads();

    // W tiles (bf16 split)
    for (int i = tid; i < COUT * 64; i += 128) {
        int co = i >> 6, k = i & 63;
        float v = (STAGE == 1) ? W[co * 67 + 3 + k] : W[co * 64 + k];
        __nv_bfloat16 h = __float2bfloat16(v);
        Wh[co * 72 + k] = h;
        Wl[co * 72 + k] = __float2bfloat16(v - __bfloat162float(h));
    }
    if (STAGE == 1)
        for (int i = tid; i < 192; i += 128) {
            int co = i / 3, c = i - co * 3;
            wloc[co * 4 + c] = W[co * 67 + c];
        }

    // A tile (bf16 split)
    for (int g = tid; g < SPB * 4; g += 128) {
        int sl = g >> 2, seg = g & 3;
        if (STAGE == 1) {
            int s = sbase + sl;
            int nidx = idx[s];
            int b = s >> 15;
            const float4* fr = (const float4*)(featT + ((size_t)(b * NPTS + nidx)) * 64 + seg * 16);
#pragma unroll
            for (int i = 0; i < 4; i++) {
                float4 v = fr[i];
                int c = sl * 72 + seg * 16 + i * 4;
                splitStore(Ah, Al, c, v.x, v.y);
                splitStore(Ah, Al, c + 2, v.z, v.w);
            }
            if (seg == 0) {
                int m = (s >> 5) & (MQ - 1);
                const float* lp = loc + ((size_t)(b * NPTS + nidx)) * 3;
                const float* qp = newloc + ((size_t)(b * MQ + m)) * 3;
                sloc[sl * 4 + 0] = lp[0] - qp[0];
                sloc[sl * 4 + 1] = lp[1] - qp[1];
                sloc[sl * 4 + 2] = lp[2] - qp[2];
            }
        } else {
            const float4* fr = (const float4*)(src + (size_t)(sbase + sl) * 64 + seg * 16);
#pragma unroll
            for (int i = 0; i < 4; i++) {
                float4 v = fr[i];
                int c4 = seg * 16 + i * 4;
                v.x = fmaxf(0.f, fmaf(afs[c4 + 0], v.x, afs[64 + c4 + 0]));
                v.y = fmaxf(0.f, fmaf(afs[c4 + 1], v.y, afs[64 + c4 + 1]));
                v.z = fmaxf(0.f, fmaf(afs[c4 + 2], v.z, afs[64 + c4 + 2]));
                v.w = fmaxf(0.f, fmaf(afs[c4 + 3], v.w, afs[64 + c4 + 3]));
                int c = sl * 72 + c4;
                splitStore(Ah, Al, c, v.x, v.y);
                splitStore(Ah, Al, c + 2, v.z, v.w);
            }
        }
    }
    __syncthreads();

    int r = lane >> 2, c2 = (lane & 3) * 2;
    float acc[MT][NT][4];
    if (STAGE == 1) {
#pragma unroll
        for (int t = 0; t < MT; t++) {
            int row0 = warp * (MT * 16) + t * 16 + r;
            float x0 = sloc[row0 * 4], y0 = sloc[row0 * 4 + 1], z0 = sloc[row0 * 4 + 2];
            float x1 = sloc[(row0 + 8) * 4], y1 = sloc[(row0 + 8) * 4 + 1], z1 = sloc[(row0 + 8) * 4 + 2];
#pragma unroll
            for (int n = 0; n < NT; n++)
#pragma unroll
                for (int cc = 0; cc < 2; cc++) {
                    int co = n * 8 + c2 + cc;
                    float wx = wloc[co * 4], wy = wloc[co * 4 + 1], wz = wloc[co * 4 + 2];
                    acc[t][n][cc]     = x0 * wx + y0 * wy + z0 * wz;
                    acc[t][n][2 + cc] = x1 * wx + y1 * wy + z1 * wz;
                }
        }
    } else {
#pragma unroll
        for (int t = 0; t < MT; t++)
#pragma unroll
            for (int n = 0; n < NT; n++)
#pragma unroll
                for (int p = 0; p < 4; p++) acc[t][n][p] = 0.f;
    }

    uint32_t aAh = (uint32_t)__cvta_generic_to_shared(Ah);
    uint32_t aAl = (uint32_t)__cvta_generic_to_shared(Al);
    uint32_t aWh = (uint32_t)__cvta_generic_to_shared(Wh);
    uint32_t aWl = (uint32_t)__cvta_generic_to_shared(Wl);

#pragma unroll
    for (int k = 0; k < 4; k++) {
        uint32_t ah[MT][4], al[MT][4];
#pragma unroll
        for (int t = 0; t < MT; t++) {
            uint32_t ao = (warp * (MT * 16) + t * 16 + (lane & 15)) * 144
                        + k * 32 + (lane >> 4) * 16;
            ldm4(ah[t], aAh + ao);
            ldm4(al[t], aAl + ao);
        }
#pragma unroll
        for (int p = 0; p < NT / 2; p++) {
            uint32_t bo = (p * 16 + (lane & 7) + ((lane >> 4) & 1) * 8) * 144
                        + k * 32 + ((lane >> 3) & 1) * 16;
            uint32_t bh[4], bl[4];
            ldm4(bh, aWh + bo);
            ldm4(bl, aWl + bo);
#pragma unroll
            for (int t = 0; t < MT; t++) {
                mma_bf16(acc[t][2 * p],     ah[t], bh[0], bh[1]);
                mma_bf16(acc[t][2 * p],     ah[t], bl[0], bl[1]);
                mma_bf16(acc[t][2 * p],     al[t], bh[0], bh[1]);
                mma_bf16(acc[t][2 * p + 1], ah[t], bh[2], bh[3]);
                mma_bf16(acc[t][2 * p + 1], ah[t], bl[2], bl[3]);
                mma_bf16(acc[t][2 * p + 1], al[t], bh[2], bh[3]);
            }
        }
    }

    // epilogue: y store (stage1/2), BN partials, stage3 max/min over k
#pragma unroll
    for (int n = 0; n < NT; n++) {
        float ps0 = 0.f, ps1 = 0.f, pq0 = 0.f, pq1 = 0.f;
        float mx0 = -3.4e38f, mx1 = -3.4e38f, mn0 = 3.4e38f, mn1 = 3.4e38f;
#pragma unroll
        for (int t = 0; t < MT; t++) {
            float d0 = acc[t][n][0], d1 = acc[t][n][1];
            float d2 = acc[t][n][2], d3 = acc[t][n][3];
            if (STAGE < 3) {
                int row = sbase + warp * (MT * 16) + t * 16 + r;
                *(float2*)(yout + (size_t)row * 64 + n * 8 + c2) = make_float2(d0, d1);
                *(float2*)(yout + (size_t)(row + 8) * 64 + n * 8 + c2) = make_float2(d2, d3);
            }
            ps0 += d0 + d2; ps1 += d1 + d3;
            pq0 += d0 * d0 + d2 * d2; pq1 += d1 * d1 + d3 * d3;
            if (STAGE == 3) {
                mx0 = fmaxf(d0, d2); mx1 = fmaxf(d1, d3);
                mn0 = fminf(d0, d2); mn1 = fminf(d1, d3);
            }
        }
#pragma unroll
        for (int off = 4; off <= 16; off <<= 1) {
            ps0 += __shfl_xor_sync(FULLM, ps0, off);
            ps1 += __shfl_xor_sync(FULLM, ps1, off);
            pq0 += __shfl_xor_sync(FULLM, pq0, off);
            pq1 += __shfl_xor_sync(FULLM, pq1, off);
            if (STAGE == 3) {
                mx0 = fmaxf(mx0, __shfl_xor_sync(FULLM, mx0, off));
                mx1 = fmaxf(mx1, __shfl_xor_sync(FULLM, mx1, off));
                mn0 = fminf(mn0, __shfl_xor_sync(FULLM, mn0, off));
                mn1 = fminf(mn1, __shfl_xor_sync(FULLM, mn1, off));
            }
        }
        if (lane < 4) {
            int ch = n * 8 + c2;
            sps[warp * COUT + ch] = ps0;  sps[warp * COUT + ch + 1] = ps1;
            spq[warp * COUT + ch] = pq0;  spq[warp * COUT + ch + 1] = pq1;
            if (STAGE == 3) {
                smx[warp * COUT + ch] = mx0;  smx[warp * COUT + ch + 1] = mx1;
                smn[warp * COUT + ch] = mn0;  smn[warp * COUT + ch + 1] = mn1;
            }
        }
    }
    __syncthreads();
    for (int ch = tid; ch < COUT; ch += 128) {
        float a = sps[ch] + sps[COUT + ch] + sps[2 * COUT + ch] + sps[3 * COUT + ch];
        float q = spq[ch] + spq[COUT + ch] + spq[2 * COUT + ch] + spq[3 * COUT + ch];
        psum[(size_t)ch * 8192 + blk] = a;
        psq [(size_t)ch * 8192 + blk] = q;
    }
    if (STAGE == 3) {
        // warps 0,1 cover m0 = sbase/32; warps 2,3 cover m0+1
        for (int i = tid; i < 256; i += 128) {
            int h = i >> 7, ch = i & 127;
            int m = (sbase >> 5) + h;
            ymax[(size_t)m * 128 + ch] =
                fmaxf(smx[(2 * h) * 128 + ch], smx[(2 * h + 1) * 128 + ch]);
            ymin[(size_t)m * 128 + ch] =
                fminf(smn[(2 * h) * 128 + ch], smn[(2 * h + 1) * 128 + ch]);
        }
    }
}

// ---------------- BN finalize ----------------------------------------------
__global__ void bn_finalize(const float* __restrict__ psum, const float* __restrict__ psq,
                            const float* __restrict__ g, const float* __restrict__ beta,
                            float* __restrict__ aff, int NB)
{
    int ch = blockIdx.x, tid = threadIdx.x;
    __shared__ float s1[256], s2[256];
    float a = 0.f, q = 0.f;
    for (int i = tid; i < NB; i += 256) {
        a += psum[(size_t)ch * 8192 + i];
        q += psq [(size_t)ch * 8192 + i];
    }
    s1[tid] = a; s2[tid] = q; __syncthreads();
    for (int st = 128; st > 0; st >>= 1) {
        if (tid < st) { s1[tid] += s1[tid + st]; s2[tid] += s2[tid + st]; }
        __syncthreads();
    }
    if (tid == 0) {
        const float invS = 1.0f / (float)S_TOTAL;
        float mu = s1[0] * invS;
        float var = s2[0] * invS - mu * mu;
        float rs = rsqrtf(var + 1e-5f);
        float aa = g[ch] * rs;
        aff[ch] = aa;
        aff[128 + ch] = beta[ch] - mu * aa;
    }
}

// ---------------- final: affine3 + relu on k-extremum, transpose -----------
__global__ __launch_bounds__(256) void final_kernel(const float* __restrict__ ymax,
                                                    const float* __restrict__ ymin,
                                                    const float* __restrict__ aff,
                                                    float* __restrict__ out)
{
    __shared__ float t[128 * 65];
    int b = blockIdx.x >> 4;
    int mg = blockIdx.x & 15;
    int tid = threadIdx.x;
    for (int i = tid; i < 8192; i += 256) {
        int m = i >> 7, ch = i & 127;
        float a = aff[ch], cc = aff[128 + ch];
        size_t base = ((size_t)(b * MQ + mg * 64 + m)) * 128 + ch;
        float val = (a > 0.f) ? ymax[base] : ymin[base];
        t[ch * 65 + m] = fmaxf(0.f, fmaf(a, val, cc));
    }
    __syncthreads();
    for (int i = tid; i < 8192; i += 256) {
        int ch = i >> 6, m = i & 63;
        out[((size_t)(b * 128 + ch)) * MQ + mg * 64 + m] = t[ch * 65 + m];
    }
}

// ---------------- launch ----------------------------------------------------
extern "C" void kernel_launch(void* const* d_in, const int* in_sizes, int n_in,
                              void* d_out, int out_size)
{
    const float* loc    = (const float*)d_in[0];
    const float* newloc = (const float*)d_in[1];
    const float* feats  = (const float*)d_in[2];
    const float* W1 = (const float*)d_in[3];
    const float* g1 = (const float*)d_in[4];
    const float* b1 = (const float*)d_in[5];
    const float* W2 = (const float*)d_in[6];
    const float* g2 = (const float*)d_in[7];
    const float* b2 = (const float*)d_in[8];
    const float* W3 = (const float*)d_in[9];
    const float* g3 = (const float*)d_in[10];
    const float* b3 = (const float*)d_in[11];
    float* out = (float*)d_out;

    int*   idx   = nullptr;  cudaGetSymbolAddress((void**)&idx,   g_idx);
    float* featT = nullptr;  cudaGetSymbolAddress((void**)&featT, g_featT);
    float* y1    = nullptr;  cudaGetSymbolAddress((void**)&y1,    g_y1);
    float* y2    = nullptr;  cudaGetSymbolAddress((void**)&y2,    g_y2);
    float* ymax  = nullptr;  cudaGetSymbolAddress((void**)&ymax,  g_ymax);
    float* ymin  = nullptr;  cudaGetSymbolAddress((void**)&ymin,  g_ymin);
    float* psum  = nullptr;  cudaGetSymbolAddress((void**)&psum,  g_psum);
    float* psq   = nullptr;  cudaGetSymbolAddress((void**)&psq,   g_psq);
    float* aff   = nullptr;  cudaGetSymbolAddress((void**)&aff,   g_aff);

    const int SM1 = 2*(128*144) + 2*(64*144) + (128+512+256+8*64)*4 + 2048;
    const int SM3 = 2*(64*144)  + 2*(128*144) + (128+512+256+16*128)*4 + 2048;
    cudaFuncSetAttribute(knnT_kernel, cudaFuncAttributeMaxDynamicSharedMemorySize, 49152);
    cudaFuncSetAttribute(gemm_mma<1>, cudaFuncAttributeMaxDynamicSharedMemorySize, SM1);
    cudaFuncSetAttribute(gemm_mma<2>, cudaFuncAttributeMaxDynamicSharedMemorySize, SM1);
    cudaFuncSetAttribute(gemm_mma<3>, cudaFuncAttributeMaxDynamicSharedMemorySize, SM3);

    knnT_kernel<<<512, 256, 49152>>>(loc, newloc, feats, featT, idx);

    gemm_mma<1><<<4096, 128, SM1>>>(W1, nullptr, nullptr, y1, nullptr, nullptr,
                                    psum, psq, idx, loc, newloc, featT);
    bn_finalize<<<64, 256>>>(psum, psq, g1, b1, aff + 0 * 256, 4096);

    gemm_mma<2><<<4096, 128, SM1>>>(W2, y1, aff + 0 * 256, y2, nullptr, nullptr,
                                    psum, psq, idx, loc, newloc, featT);
    bn_finalize<<<64, 256>>>(psum, psq, g2, b2, aff + 1 * 256, 4096);

    gemm_mma<3><<<8192, 128, SM3>>>(W3, y2, aff + 1 * 256, nullptr, ymax, ymin,
                                    psum, psq, idx, loc, newloc, featT);
    bn_finalize<<<128, 256>>>(psum, psq, g3, b3, aff + 2 * 256, 8192);

    final_kernel<<<BB * 16, 256>>>(ymax, ymin, aff + 2 * 256, out);
    (void)in_sizes; (void)n_in; (void)out_size;
}

// round 14
// speedup vs baseline: 1.6979x; 1.1529x over previous
#include <cuda_runtime.h>
#include <cuda_bf16.h>
#include <cstdint>

#define BB    16
#define NPTS  4096
#define MQ    1024
#define KNB   32
#define S_TOTAL (BB*MQ*KNB)
#define FULLM 0xffffffffu

// ---------------- device scratch -------------------------------------------
__device__ __align__(16) int   g_idx[S_TOTAL];
__device__ __align__(16) float g_featT[BB*NPTS*64];
__device__ __align__(16) float g_y1[(size_t)S_TOTAL*64];
__device__ __align__(16) float g_y2[(size_t)S_TOTAL*64];
__device__ __align__(16) float g_ymax[BB*MQ*128];
__device__ __align__(16) float g_ymin[BB*MQ*128];
__device__ __align__(16) float g_psum[128*8192];
__device__ __align__(16) float g_psq [128*8192];
__device__ __align__(16) float g_aff[3][256];

// ---------------- mma helpers ----------------------------------------------
__device__ __forceinline__ void ldm4(uint32_t* r, uint32_t addr) {
    asm volatile("ldmatrix.sync.aligned.m8n8.x4.shared.b16 {%0,%1,%2,%3}, [%4];"
        : "=r"(r[0]), "=r"(r[1]), "=r"(r[2]), "=r"(r[3]) : "r"(addr));
}
__device__ __forceinline__ void mma_bf16(float* d, const uint32_t* a,
                                         uint32_t b0, uint32_t b1) {
    asm volatile("mma.sync.aligned.m16n8k16.row.col.f32.bf16.bf16.f32 "
        "{%0,%1,%2,%3}, {%4,%5,%6,%7}, {%8,%9}, {%0,%1,%2,%3};"
        : "+f"(d[0]), "+f"(d[1]), "+f"(d[2]), "+f"(d[3])
        : "r"(a[0]), "r"(a[1]), "r"(a[2]), "r"(a[3]), "r"(b0), "r"(b1));
}
// pack two fp32 into bf16x2 hi + residual-lo (low half = first arg, memory order)
__device__ __forceinline__ void mk2(float x, float y, uint32_t& h, uint32_t& l) {
    __nv_bfloat162 hh = __floats2bfloat162_rn(x, y);
    h = *(uint32_t*)&hh;
    __nv_bfloat162 ll = __floats2bfloat162_rn(x - __low2float(hh), y - __high2float(hh));
    l = *(uint32_t*)&ll;
}

// ---------------- KNN + features transpose fused ---------------------------
__global__ __launch_bounds__(256) void knnT_kernel(const float* __restrict__ loc,
                                                   const float* __restrict__ newloc,
                                                   const float* __restrict__ feats,
                                                   float* __restrict__ featT,
                                                   int* __restrict__ idxout)
{
    extern __shared__ float smem[];
    int b = blockIdx.x >> 5;
    int grp = blockIdx.x & 31;
    int tid = threadIdx.x;
    {
        int n0 = grp * 128;
        for (int i = tid; i < 64 * 128; i += 256) {
            int c = i >> 7, n = i & 127;
            smem[n * 65 + c] = feats[((size_t)b * 64 + c) * NPTS + n0 + n];
        }
        __syncthreads();
        for (int i = tid; i < 64 * 128; i += 256) {
            int n = i >> 6, c = i & 63;
            featT[((size_t)b * NPTS + n0 + n) * 64 + c] = smem[n * 65 + c];
        }
        __syncthreads();
    }
    float* sx = smem; float* sy = smem + NPTS; float* sz = smem + 2 * NPTS;
    for (int i = tid; i < NPTS; i += 256) {
        const float* p = loc + ((size_t)b * NPTS + i) * 3;
        sx[i] = p[0]; sy[i] = p[1]; sz[i] = p[2];
    }
    __syncthreads();
    int warp = tid >> 5, lane = tid & 31;
    for (int j = 0; j < 4; j++) {
        int m = grp * 32 + j * 8 + warp;
        const float* q = newloc + ((size_t)b * MQ + m) * 3;
        float qx = q[0], qy = q[1], qz = q[2];
        float q2 = qx * qx + qy * qy + qz * qz;
        float bv = 3.4e38f;  int bi = 0x7fffffff;
        for (int cg = 0; cg < NPTS / 128; cg++) {
            float tv = __shfl_sync(FULLM, bv, 31);
            int   ti = __shfl_sync(FULLM, bi, 31);
            float d2v[4];
#pragma unroll
            for (int u = 0; u < 4; u++) {
                int p = (cg * 4 + u) * 32 + lane;
                float x = sx[p], y = sy[p], z = sz[p];
                float w = x * x + y * y + z * z;
                d2v[u] = (q2 + w) - 2.0f * (qx * x + qy * y + qz * z);
            }
#pragma unroll
            for (int u = 0; u < 4; u++) {
                int di = (cg * 4 + u) * 32 + lane;
                bool acc = (d2v[u] < tv) || (d2v[u] == tv && di < ti);
                unsigned bm = __ballot_sync(FULLM, acc);
                if (!bm) continue;
                while (bm) {
                    int src = __ffs(bm) - 1; bm &= bm - 1;
                    float nv = __shfl_sync(FULLM, d2v[u], src);
                    int   ni = (cg * 4 + u) * 32 + src;
                    bool lt = (bv < nv) || (bv == nv && bi < ni);
                    int pos = __popc(__ballot_sync(FULLM, lt));
                    float pv = __shfl_up_sync(FULLM, bv, 1);
                    int   pi = __shfl_up_sync(FULLM, bi, 1);
                    if (lane == pos)      { bv = nv; bi = ni; }
                    else if (lane > pos)  { bv = pv; bi = pi; }
                }
                tv = __shfl_sync(FULLM, bv, 31);
                ti = __shfl_sync(FULLM, bi, 31);
            }
        }
        idxout[((size_t)b * MQ + m) * KNB + lane] = bi;
    }
}

// ---------------- tensor-core GEMM stage, register-direct A ----------------
// A fragments built in registers straight from global (no A smem tile).
// STAGE 1: gather, COUT=64, SPB=128, loc channels via fp32 acc-init.
// STAGE 2: affine+relu(y1), COUT=64, SPB=128.
// STAGE 3: affine+relu(y2), COUT=128, SPB=64, fused k-max/min.
template<int STAGE>
__global__ __launch_bounds__(128, 4) void gemm_mma(
    const float* __restrict__ W, const float* __restrict__ src,
    const float* __restrict__ aff, float* __restrict__ yout,
    float* __restrict__ ymax, float* __restrict__ ymin,
    float* __restrict__ psum, float* __restrict__ psq,
    const int* __restrict__ idx, const float* __restrict__ loc,
    const float* __restrict__ newloc, const float* __restrict__ featT)
{
    constexpr int COUT = (STAGE == 3) ? 128 : 64;
    constexpr int SPB  = (STAGE == 3) ? 64 : 128;
    constexpr int NT   = COUT / 8;
    constexpr int MT   = SPB / 64;
    constexpr int WBYT = COUT * 72 * 2;

    extern __shared__ __align__(16) char smc[];
    __nv_bfloat16* Wh = (__nv_bfloat16*)smc;
    __nv_bfloat16* Wl = (__nv_bfloat16*)(smc + WBYT);
    float* afs  = (float*)(smc + 2 * WBYT);   // [a(64) | c(64)]
    float* wloc = afs + 128;                  // 64*4 (stage1)
    float* sps  = wloc + 256;                 // 4*COUT
    float* spq  = sps + 4 * COUT;
    float* smx  = spq + 4 * COUT;
    float* smn  = smx + 4 * COUT;

    int tid = threadIdx.x, warp = tid >> 5, lane = tid & 31;
    int blk = blockIdx.x;
    int sbase = blk * SPB;
    int r = lane >> 2, cg = lane & 3, c2 = cg * 2;
    int wb = warp * (MT * 16);

    if (STAGE > 1)
        afs[tid] = (tid < 64) ? aff[tid] : aff[128 + tid - 64];

    for (int i = tid; i < COUT * 64; i += 128) {
        int co = i >> 6, k = i & 63;
        float v = (STAGE == 1) ? W[co * 67 + 3 + k] : W[co * 64 + k];
        __nv_bfloat16 h = __float2bfloat16(v);
        Wh[co * 72 + k] = h;
        Wl[co * 72 + k] = __float2bfloat16(v - __bfloat162float(h));
    }
    if (STAGE == 1)
        for (int i = tid; i < 192; i += 128) {
            int co = i / 3, c = i - co * 3;
            wloc[co * 4 + c] = W[co * 67 + c];
        }
    __syncthreads();

    // per-lane row pointers
    const float* row0[MT];
    const float* row1[MT];
    float acc[MT][NT][4];
#pragma unroll
    for (int t = 0; t < MT; t++) {
        int s0 = sbase + wb + t * 16 + r;
        int s1 = s0 + 8;
        if (STAGE == 1) {
            int n0 = idx[s0], n1 = idx[s1];
            int b = s0 >> 15;
            row0[t] = featT + (size_t)(b * NPTS + n0) * 64;
            row1[t] = featT + (size_t)(b * NPTS + n1) * 64;
            const float* lp0 = loc + (size_t)(b * NPTS + n0) * 3;
            const float* lp1 = loc + (size_t)(b * NPTS + n1) * 3;
            const float* qp0 = newloc + (size_t)(b * MQ + ((s0 >> 5) & (MQ - 1))) * 3;
            const float* qp1 = newloc + (size_t)(b * MQ + ((s1 >> 5) & (MQ - 1))) * 3;
            float rx0 = lp0[0] - qp0[0], ry0 = lp0[1] - qp0[1], rz0 = lp0[2] - qp0[2];
            float rx1 = lp1[0] - qp1[0], ry1 = lp1[1] - qp1[1], rz1 = lp1[2] - qp1[2];
#pragma unroll
            for (int n = 0; n < NT; n++)
#pragma unroll
                for (int cc = 0; cc < 2; cc++) {
                    const float* wl = wloc + (n * 8 + c2 + cc) * 4;
                    acc[t][n][cc]     = rx0 * wl[0] + ry0 * wl[1] + rz0 * wl[2];
                    acc[t][n][2 + cc] = rx1 * wl[0] + ry1 * wl[1] + rz1 * wl[2];
                }
        } else {
            row0[t] = src + (size_t)s0 * 64;
            row1[t] = src + (size_t)s1 * 64;
#pragma unroll
            for (int n = 0; n < NT; n++)
#pragma unroll
                for (int p = 0; p < 4; p++) acc[t][n][p] = 0.f;
        }
    }

    uint32_t aWh = (uint32_t)__cvta_generic_to_shared(Wh);
    uint32_t aWl = (uint32_t)__cvta_generic_to_shared(Wl);

#pragma unroll
    for (int k = 0; k < 4; k++) {
        int c0 = c2 + k * 16;
        uint32_t ah[MT][4], al[MT][4];
#pragma unroll
        for (int t = 0; t < MT; t++) {
            float2 u00 = *(const float2*)(row0[t] + c0);
            float2 u08 = *(const float2*)(row0[t] + c0 + 8);
            float2 u10 = *(const float2*)(row1[t] + c0);
            float2 u18 = *(const float2*)(row1[t] + c0 + 8);
            if (STAGE > 1) {
                float2 a0 = *(const float2*)(afs + c0);
                float2 cc0 = *(const float2*)(afs + 64 + c0);
                float2 a8 = *(const float2*)(afs + c0 + 8);
                float2 cc8 = *(const float2*)(afs + 64 + c0 + 8);
                u00.x = fmaxf(0.f, fmaf(a0.x, u00.x, cc0.x));
                u00.y = fmaxf(0.f, fmaf(a0.y, u00.y, cc0.y));
                u08.x = fmaxf(0.f, fmaf(a8.x, u08.x, cc8.x));
                u08.y = fmaxf(0.f, fmaf(a8.y, u08.y, cc8.y));
                u10.x = fmaxf(0.f, fmaf(a0.x, u10.x, cc0.x));
                u10.y = fmaxf(0.f, fmaf(a0.y, u10.y, cc0.y));
                u18.x = fmaxf(0.f, fmaf(a8.x, u18.x, cc8.x));
                u18.y = fmaxf(0.f, fmaf(a8.y, u18.y, cc8.y));
            }
            mk2(u00.x, u00.y, ah[t][0], al[t][0]);
            mk2(u10.x, u10.y, ah[t][1], al[t][1]);
            mk2(u08.x, u08.y, ah[t][2], al[t][2]);
            mk2(u18.x, u18.y, ah[t][3], al[t][3]);
        }
#pragma unroll
        for (int p = 0; p < NT / 2; p++) {
            uint32_t bo = (p * 16 + (lane & 7) + ((lane >> 4) & 1) * 8) * 144
                        + k * 32 + ((lane >> 3) & 1) * 16;
            uint32_t bh[4], bl[4];
            ldm4(bh, aWh + bo);
            ldm4(bl, aWl + bo);
#pragma unroll
            for (int t = 0; t < MT; t++) {
                mma_bf16(acc[t][2 * p],     ah[t], bh[0], bh[1]);
                mma_bf16(acc[t][2 * p],     ah[t], bl[0], bl[1]);
                mma_bf16(acc[t][2 * p],     al[t], bh[0], bh[1]);
                mma_bf16(acc[t][2 * p + 1], ah[t], bh[2], bh[3]);
                mma_bf16(acc[t][2 * p + 1], ah[t], bl[2], bl[3]);
                mma_bf16(acc[t][2 * p + 1], al[t], bh[2], bh[3]);
            }
        }
    }

    // epilogue
#pragma unroll
    for (int n = 0; n < NT; n++) {
        float ps0 = 0.f, ps1 = 0.f, pq0 = 0.f, pq1 = 0.f;
        float mx0 = -3.4e38f, mx1 = -3.4e38f, mn0 = 3.4e38f, mn1 = 3.4e38f;
#pragma unroll
        for (int t = 0; t < MT; t++) {
            float d0 = acc[t][n][0], d1 = acc[t][n][1];
            float d2 = acc[t][n][2], d3 = acc[t][n][3];
            if (STAGE < 3) {
                int row = sbase + wb + t * 16 + r;
                *(float2*)(yout + (size_t)row * 64 + n * 8 + c2) = make_float2(d0, d1);
                *(float2*)(yout + (size_t)(row + 8) * 64 + n * 8 + c2) = make_float2(d2, d3);
            }
            ps0 += d0 + d2; ps1 += d1 + d3;
            pq0 += d0 * d0 + d2 * d2; pq1 += d1 * d1 + d3 * d3;
            if (STAGE == 3) {
                mx0 = fmaxf(d0, d2); mx1 = fmaxf(d1, d3);
                mn0 = fminf(d0, d2); mn1 = fminf(d1, d3);
            }
        }
#pragma unroll
        for (int off = 4; off <= 16; off <<= 1) {
            ps0 += __shfl_xor_sync(FULLM, ps0, off);
            ps1 += __shfl_xor_sync(FULLM, ps1, off);
            pq0 += __shfl_xor_sync(FULLM, pq0, off);
            pq1 += __shfl_xor_sync(FULLM, pq1, off);
            if (STAGE == 3) {
                mx0 = fmaxf(mx0, __shfl_xor_sync(FULLM, mx0, off));
                mx1 = fmaxf(mx1, __shfl_xor_sync(FULLM, mx1, off));
                mn0 = fminf(mn0, __shfl_xor_sync(FULLM, mn0, off));
                mn1 = fminf(mn1, __shfl_xor_sync(FULLM, mn1, off));
            }
        }
        if (lane < 4) {
            int ch = n * 8 + c2;
            sps[warp * COUT + ch] = ps0;  sps[warp * COUT + ch + 1] = ps1;
            spq[warp * COUT + ch] = pq0;  spq[warp * COUT + ch + 1] = pq1;
            if (STAGE == 3) {
                smx[warp * COUT + ch] = mx0;  smx[warp * COUT + ch + 1] = mx1;
                smn[warp * COUT + ch] = mn0;  smn[warp * COUT + ch + 1] = mn1;
            }
        }
    }
    __syncthreads();
    for (int ch = tid; ch < COUT; ch += 128) {
        float a = sps[ch] + sps[COUT + ch] + sps[2 * COUT + ch] + sps[3 * COUT + ch];
        float q = spq[ch] + spq[COUT + ch] + spq[2 * COUT + ch] + spq[3 * COUT + ch];
        psum[(size_t)ch * 8192 + blk] = a;
        psq [(size_t)ch * 8192 + blk] = q;
    }
    if (STAGE == 3) {
        for (int i = tid; i < 256; i += 128) {
            int h = i >> 7, ch = i & 127;
            int m = (sbase >> 5) + h;
            ymax[(size_t)m * 128 + ch] =
                fmaxf(smx[(2 * h) * 128 + ch], smx[(2 * h + 1) * 128 + ch]);
            ymin[(size_t)m * 128 + ch] =
                fminf(smn[(2 * h) * 128 + ch], smn[(2 * h + 1) * 128 + ch]);
        }
    }
}

// ---------------- BN finalize ----------------------------------------------
__global__ void bn_finalize(const float* __restrict__ psum, const float* __restrict__ psq,
                            const float* __restrict__ g, const float* __restrict__ beta,
                            float* __restrict__ aff, int NB)
{
    int ch = blockIdx.x, tid = threadIdx.x;
    __shared__ float s1[256], s2[256];
    float a = 0.f, q = 0.f;
    for (int i = tid; i < NB; i += 256) {
        a += psum[(size_t)ch * 8192 + i];
        q += psq [(size_t)ch * 8192 + i];
    }
    s1[tid] = a; s2[tid] = q; __syncthreads();
    for (int st = 128; st > 0; st >>= 1) {
        if (tid < st) { s1[tid] += s1[tid + st]; s2[tid] += s2[tid + st]; }
        __syncthreads();
    }
    if (tid == 0) {
        const float invS = 1.0f / (float)S_TOTAL;
        float mu = s1[0] * invS;
        float var = s2[0] * invS - mu * mu;
        float rs = rsqrtf(var + 1e-5f);
        float aa = g[ch] * rs;
        aff[ch] = aa;
        aff[128 + ch] = beta[ch] - mu * aa;
    }
}

// ---------------- final: affine3 + relu on k-extremum, transpose -----------
__global__ __launch_bounds__(256) void final_kernel(const float* __restrict__ ymax,
                                                    const float* __restrict__ ymin,
                                                    const float* __restrict__ aff,
                                                    float* __restrict__ out)
{
    __shared__ float t[128 * 65];
    int b = blockIdx.x >> 4;
    int mg = blockIdx.x & 15;
    int tid = threadIdx.x;
    for (int i = tid; i < 8192; i += 256) {
        int m = i >> 7, ch = i & 127;
        float a = aff[ch], cc = aff[128 + ch];
        size_t base = ((size_t)(b * MQ + mg * 64 + m)) * 128 + ch;
        float val = (a > 0.f) ? ymax[base] : ymin[base];
        t[ch * 65 + m] = fmaxf(0.f, fmaf(a, val, cc));
    }
    __syncthreads();
    for (int i = tid; i < 8192; i += 256) {
        int ch = i >> 6, m = i & 63;
        out[((size_t)(b * 128 + ch)) * MQ + mg * 64 + m] = t[ch * 65 + m];
    }
}

// ---------------- launch ----------------------------------------------------
extern "C" void kernel_launch(void* const* d_in, const int* in_sizes, int n_in,
                              void* d_out, int out_size)
{
    const float* loc    = (const float*)d_in[0];
    const float* newloc = (const float*)d_in[1];
    const float* feats  = (const float*)d_in[2];
    const float* W1 = (const float*)d_in[3];
    const float* g1 = (const float*)d_in[4];
    const float* b1 = (const float*)d_in[5];
    const float* W2 = (const float*)d_in[6];
    const float* g2 = (const float*)d_in[7];
    const float* b2 = (const float*)d_in[8];
    const float* W3 = (const float*)d_in[9];
    const float* g3 = (const float*)d_in[10];
    const float* b3 = (const float*)d_in[11];
    float* out = (float*)d_out;

    int*   idx   = nullptr;  cudaGetSymbolAddress((void**)&idx,   g_idx);
    float* featT = nullptr;  cudaGetSymbolAddress((void**)&featT, g_featT);
    float* y1    = nullptr;  cudaGetSymbolAddress((void**)&y1,    g_y1);
    float* y2    = nullptr;  cudaGetSymbolAddress((void**)&y2,    g_y2);
    float* ymax  = nullptr;  cudaGetSymbolAddress((void**)&ymax,  g_ymax);
    float* ymin  = nullptr;  cudaGetSymbolAddress((void**)&ymin,  g_ymin);
    float* psum  = nullptr;  cudaGetSymbolAddress((void**)&psum,  g_psum);
    float* psq   = nullptr;  cudaGetSymbolAddress((void**)&psq,   g_psq);
    float* aff   = nullptr;  cudaGetSymbolAddress((void**)&aff,   g_aff);

    // smem: 2*W tile + floats [afs 128 | wloc 256 | sps 4C | spq 4C | smx 4C | smn 4C]
    const int SM12 = 2 * (64 * 144)  + (128 + 256 + 16 * 64)  * 4;   // 24064
    const int SM3  = 2 * (128 * 144) + (128 + 256 + 16 * 128) * 4;   // 46592
    cudaFuncSetAttribute(knnT_kernel, cudaFuncAttributeMaxDynamicSharedMemorySize, 49152);

    knnT_kernel<<<512, 256, 49152>>>(loc, newloc, feats, featT, idx);

    gemm_mma<1><<<4096, 128, SM12>>>(W1, nullptr, nullptr, y1, nullptr, nullptr,
                                     psum, psq, idx, loc, newloc, featT);
    bn_finalize<<<64, 256>>>(psum, psq, g1, b1, aff + 0 * 256, 4096);

    gemm_mma<2><<<4096, 128, SM12>>>(W2, y1, aff + 0 * 256, y2, nullptr, nullptr,
                                     psum, psq, idx, loc, newloc, featT);
    bn_finalize<<<64, 256>>>(psum, psq, g2, b2, aff + 1 * 256, 4096);

    gemm_mma<3><<<8192, 128, SM3>>>(W3, y2, aff + 1 * 256, nullptr, ymax, ymin,
                                    psum, psq, idx, loc, newloc, featT);
    bn_finalize<<<128, 256>>>(psum, psq, g3, b3, aff + 2 * 256, 8192);

    final_kernel<<<BB * 16, 256>>>(ymax, ymin, aff + 2 * 256, out);
    (void)in_sizes; (void)n_in; (void)out_size;
}

// round 15
// speedup vs baseline: 1.7078x; 1.0058x over previous
#include <cuda_runtime.h>
#include <cuda_bf16.h>
#include <cstdint>

#define BB    16
#define NPTS  4096
#define MQ    1024
#define KNB   32
#define S_TOTAL (BB*MQ*KNB)
#define FULLM 0xffffffffu

typedef unsigned long long ull;

// ---------------- device scratch -------------------------------------------
__device__ __align__(16) int   g_idx[S_TOTAL];
__device__ __align__(16) float g_featT[BB*NPTS*64];
__device__ __align__(16) float g_y1[(size_t)S_TOTAL*64];
__device__ __align__(16) float g_y2[(size_t)S_TOTAL*64];
__device__ __align__(16) float g_ymax[BB*MQ*128];
__device__ __align__(16) float g_ymin[BB*MQ*128];
__device__ __align__(16) float g_psum[128*8192];
__device__ __align__(16) float g_psq [128*8192];
__device__ __align__(16) float g_aff[3][256];

// ---------------- mma helpers ----------------------------------------------
__device__ __forceinline__ void ldm4(uint32_t* r, uint32_t addr) {
    asm volatile("ldmatrix.sync.aligned.m8n8.x4.shared.b16 {%0,%1,%2,%3}, [%4];"
        : "=r"(r[0]), "=r"(r[1]), "=r"(r[2]), "=r"(r[3]) : "r"(addr));
}
__device__ __forceinline__ void mma_bf16(float* d, const uint32_t* a,
                                         uint32_t b0, uint32_t b1) {
    asm volatile("mma.sync.aligned.m16n8k16.row.col.f32.bf16.bf16.f32 "
        "{%0,%1,%2,%3}, {%4,%5,%6,%7}, {%8,%9}, {%0,%1,%2,%3};"
        : "+f"(d[0]), "+f"(d[1]), "+f"(d[2]), "+f"(d[3])
        : "r"(a[0]), "r"(a[1]), "r"(a[2]), "r"(a[3]), "r"(b0), "r"(b1));
}
__device__ __forceinline__ void mk2(float x, float y, uint32_t& h, uint32_t& l) {
    __nv_bfloat162 hh = __floats2bfloat162_rn(x, y);
    h = *(uint32_t*)&hh;
    __nv_bfloat162 ll = __floats2bfloat162_rn(x - __low2float(hh), y - __high2float(hh));
    l = *(uint32_t*)&ll;
}
// monotone float->u32 map (lexicographic over all floats incl. negatives)
__device__ __forceinline__ uint32_t fmono(float f) {
    uint32_t u = __float_as_uint(f);
    return u ^ ((uint32_t)((int)u >> 31) | 0x80000000u);
}

// ---------------- KNN + features transpose fused ---------------------------
__global__ __launch_bounds__(256) void knnT_kernel(const float* __restrict__ loc,
                                                   const float* __restrict__ newloc,
                                                   const float* __restrict__ feats,
                                                   float* __restrict__ featT,
                                                   int* __restrict__ idxout)
{
    extern __shared__ float smem[];
    int b = blockIdx.x >> 5;
    int grp = blockIdx.x & 31;
    int tid = threadIdx.x;
    {
        int n0 = grp * 128;
        for (int i = tid; i < 64 * 128; i += 256) {
            int c = i >> 7, n = i & 127;
            smem[n * 65 + c] = feats[((size_t)b * 64 + c) * NPTS + n0 + n];
        }
        __syncthreads();
        for (int i = tid; i < 64 * 128; i += 256) {
            int n = i >> 6, c = i & 63;
            featT[((size_t)b * NPTS + n0 + n) * 64 + c] = smem[n * 65 + c];
        }
        __syncthreads();
    }
    float* sx = smem; float* sy = smem + NPTS; float* sz = smem + 2 * NPTS;
    for (int i = tid; i < NPTS; i += 256) {
        const float* p = loc + ((size_t)b * NPTS + i) * 3;
        sx[i] = p[0]; sy[i] = p[1]; sz[i] = p[2];
    }
    __syncthreads();

    int warp = tid >> 5, lane = tid & 31;
    for (int j = 0; j < 4; j++) {
        int m = grp * 32 + j * 8 + warp;
        const float* q = newloc + ((size_t)b * MQ + m) * 3;
        float qx = q[0], qy = q[1], qz = q[2];
        float q2 = qx * qx + qy * qy + qz * qz;

        // phase 1: lane-local top-2 (keys = (mono(d2)<<32)|idx)
        ull k1 = ~0ull, k2 = ~0ull;
#pragma unroll 4
        for (int it = 0; it < 128; it++) {
            int p = it * 32 + lane;
            float x = sx[p], y = sy[p], z = sz[p];
            float w = x * x + y * y + z * z;
            float d2 = (q2 + w) - 2.0f * (qx * x + qy * y + qz * z);
            ull key = ((ull)fmono(d2) << 32) | (uint32_t)p;
            if (key < k2) {
                if (key < k1) { k2 = k1; k1 = key; }
                else          { k2 = key; }
            }
        }

        // phase 2: sort A(=k1s) and B(=k2s) ascending across lanes, then
        // bitonic lowest-32 merge -> C sorted ascending (lane l = l-th best)
        ull A = k1, B = k2;
#pragma unroll
        for (int k = 2; k <= 32; k <<= 1) {
#pragma unroll
            for (int jj = k >> 1; jj; jj >>= 1) {
                bool keep = ((lane & jj) == 0) == ((lane & k) == 0);
                ull oa = __shfl_xor_sync(FULLM, A, jj);
                ull ob = __shfl_xor_sync(FULLM, B, jj);
                A = (keep == (A < oa)) ? A : oa;
                B = (keep == (B < ob)) ? B : ob;
            }
        }
        ull Br = __shfl_sync(FULLM, B, 31 - lane);
        ull C = (A < Br) ? A : Br;
#pragma unroll
        for (int jj = 16; jj; jj >>= 1) {
            bool lower = (lane & jj) == 0;
            ull o = __shfl_xor_sync(FULLM, C, jj);
            C = (lower == (C < o)) ? C : o;
        }
        ull Tp = __shfl_sync(FULLM, C, 31);

        // phase 3: rescan for candidates ranked >=3 in their lane, < Tp
#pragma unroll 4
        for (int it = 0; it < 128; it++) {
            int p = it * 32 + lane;
            float x = sx[p], y = sy[p], z = sz[p];
            float w = x * x + y * y + z * z;
            float d2 = (q2 + w) - 2.0f * (qx * x + qy * y + qz * z);
            ull key = ((ull)fmono(d2) << 32) | (uint32_t)p;
            bool miss = (key < Tp) && (key > k2);
            unsigned bm = __ballot_sync(FULLM, miss);
            while (bm) {
                int src = __ffs(bm) - 1; bm &= bm - 1;
                ull nk = __shfl_sync(FULLM, key, src);
                int pos = __popc(__ballot_sync(FULLM, C < nk));
                ull pk = __shfl_up_sync(FULLM, C, 1);
                if (lane == pos)      C = nk;
                else if (lane > pos)  C = pk;
            }
        }
        idxout[((size_t)b * MQ + m) * KNB + lane] = (int)(uint32_t)C;
    }
}

// ---------------- tensor-core GEMM stage, register-direct A ----------------
template<int STAGE>
__global__ __launch_bounds__(128, 4) void gemm_mma(
    const float* __restrict__ W, const float* __restrict__ src,
    const float* __restrict__ aff, float* __restrict__ yout,
    float* __restrict__ ymax, float* __restrict__ ymin,
    float* __restrict__ psum, float* __restrict__ psq,
    const int* __restrict__ idx, const float* __restrict__ loc,
    const float* __restrict__ newloc, const float* __restrict__ featT)
{
    constexpr int COUT = (STAGE == 3) ? 128 : 64;
    constexpr int SPB  = (STAGE == 3) ? 64 : 128;
    constexpr int NT   = COUT / 8;
    constexpr int MT   = SPB / 64;
    constexpr int WBYT = COUT * 72 * 2;

    extern __shared__ __align__(16) char smc[];
    __nv_bfloat16* Wh = (__nv_bfloat16*)smc;
    __nv_bfloat16* Wl = (__nv_bfloat16*)(smc + WBYT);
    float* afs  = (float*)(smc + 2 * WBYT);
    float* wloc = afs + 128;
    float* sps  = wloc + 256;
    float* spq  = sps + 4 * COUT;
    float* smx  = spq + 4 * COUT;
    float* smn  = smx + 4 * COUT;

    int tid = threadIdx.x, warp = tid >> 5, lane = tid & 31;
    int blk = blockIdx.x;
    int sbase = blk * SPB;
    int r = lane >> 2, cg = lane & 3, c2 = cg * 2;
    int wb = warp * (MT * 16);

    if (STAGE > 1)
        afs[tid] = (tid < 64) ? aff[tid] : aff[128 + tid - 64];

    for (int i = tid; i < COUT * 64; i += 128) {
        int co = i >> 6, k = i & 63;
        float v = (STAGE == 1) ? W[co * 67 + 3 + k] : W[co * 64 + k];
        __nv_bfloat16 h = __float2bfloat16(v);
        Wh[co * 72 + k] = h;
        Wl[co * 72 + k] = __float2bfloat16(v - __bfloat162float(h));
    }
    if (STAGE == 1)
        for (int i = tid; i < 192; i += 128) {
            int co = i / 3, c = i - co * 3;
            wloc[co * 4 + c] = W[co * 67 + c];
        }
    __syncthreads();

    const float* row0[MT];
    const float* row1[MT];
    float acc[MT][NT][4];
#pragma unroll
    for (int t = 0; t < MT; t++) {
        int s0 = sbase + wb + t * 16 + r;
        int s1 = s0 + 8;
        if (STAGE == 1) {
            int n0 = idx[s0], n1 = idx[s1];
            int b = s0 >> 15;
            row0[t] = featT + (size_t)(b * NPTS + n0) * 64;
            row1[t] = featT + (size_t)(b * NPTS + n1) * 64;
            const float* lp0 = loc + (size_t)(b * NPTS + n0) * 3;
            const float* lp1 = loc + (size_t)(b * NPTS + n1) * 3;
            const float* qp0 = newloc + (size_t)(b * MQ + ((s0 >> 5) & (MQ - 1))) * 3;
            const float* qp1 = newloc + (size_t)(b * MQ + ((s1 >> 5) & (MQ - 1))) * 3;
            float rx0 = lp0[0] - qp0[0], ry0 = lp0[1] - qp0[1], rz0 = lp0[2] - qp0[2];
            float rx1 = lp1[0] - qp1[0], ry1 = lp1[1] - qp1[1], rz1 = lp1[2] - qp1[2];
#pragma unroll
            for (int n = 0; n < NT; n++)
#pragma unroll
                for (int cc = 0; cc < 2; cc++) {
                    const float* wl = wloc + (n * 8 + c2 + cc) * 4;
                    acc[t][n][cc]     = rx0 * wl[0] + ry0 * wl[1] + rz0 * wl[2];
                    acc[t][n][2 + cc] = rx1 * wl[0] + ry1 * wl[1] + rz1 * wl[2];
                }
        } else {
            row0[t] = src + (size_t)s0 * 64;
            row1[t] = src + (size_t)s1 * 64;
#pragma unroll
            for (int n = 0; n < NT; n++)
#pragma unroll
                for (int p = 0; p < 4; p++) acc[t][n][p] = 0.f;
        }
    }

    uint32_t aWh = (uint32_t)__cvta_generic_to_shared(Wh);
    uint32_t aWl = (uint32_t)__cvta_generic_to_shared(Wl);

#pragma unroll
    for (int k = 0; k < 4; k++) {
        int c0 = c2 + k * 16;
        uint32_t ah[MT][4], al[MT][4];
#pragma unroll
        for (int t = 0; t < MT; t++) {
            float2 u00 = *(const float2*)(row0[t] + c0);
            float2 u08 = *(const float2*)(row0[t] + c0 + 8);
            float2 u10 = *(const float2*)(row1[t] + c0);
            float2 u18 = *(const float2*)(row1[t] + c0 + 8);
            if (STAGE > 1) {
                float2 a0 = *(const float2*)(afs + c0);
                float2 cc0 = *(const float2*)(afs + 64 + c0);
                float2 a8 = *(const float2*)(afs + c0 + 8);
                float2 cc8 = *(const float2*)(afs + 64 + c0 + 8);
                u00.x = fmaxf(0.f, fmaf(a0.x, u00.x, cc0.x));
                u00.y = fmaxf(0.f, fmaf(a0.y, u00.y, cc0.y));
                u08.x = fmaxf(0.f, fmaf(a8.x, u08.x, cc8.x));
                u08.y = fmaxf(0.f, fmaf(a8.y, u08.y, cc8.y));
                u10.x = fmaxf(0.f, fmaf(a0.x, u10.x, cc0.x));
                u10.y = fmaxf(0.f, fmaf(a0.y, u10.y, cc0.y));
                u18.x = fmaxf(0.f, fmaf(a8.x, u18.x, cc8.x));
                u18.y = fmaxf(0.f, fmaf(a8.y, u18.y, cc8.y));
            }
            mk2(u00.x, u00.y, ah[t][0], al[t][0]);
            mk2(u10.x, u10.y, ah[t][1], al[t][1]);
            mk2(u08.x, u08.y, ah[t][2], al[t][2]);
            mk2(u18.x, u18.y, ah[t][3], al[t][3]);
        }
#pragma unroll
        for (int p = 0; p < NT / 2; p++) {
            uint32_t bo = (p * 16 + (lane & 7) + ((lane >> 4) & 1) * 8) * 144
                        + k * 32 + ((lane >> 3) & 1) * 16;
            uint32_t bh[4], bl[4];
            ldm4(bh, aWh + bo);
            ldm4(bl, aWl + bo);
#pragma unroll
            for (int t = 0; t < MT; t++) {
                mma_bf16(acc[t][2 * p],     ah[t], bh[0], bh[1]);
                mma_bf16(acc[t][2 * p],     ah[t], bl[0], bl[1]);
                mma_bf16(acc[t][2 * p],     al[t], bh[0], bh[1]);
                mma_bf16(acc[t][2 * p + 1], ah[t], bh[2], bh[3]);
                mma_bf16(acc[t][2 * p + 1], ah[t], bl[2], bl[3]);
                mma_bf16(acc[t][2 * p + 1], al[t], bh[2], bh[3]);
            }
        }
    }

#pragma unroll
    for (int n = 0; n < NT; n++) {
        float ps0 = 0.f, ps1 = 0.f, pq0 = 0.f, pq1 = 0.f;
        float mx0 = -3.4e38f, mx1 = -3.4e38f, mn0 = 3.4e38f, mn1 = 3.4e38f;
#pragma unroll
        for (int t = 0; t < MT; t++) {
            float d0 = acc[t][n][0], d1 = acc[t][n][1];
            float d2 = acc[t][n][2], d3 = acc[t][n][3];
            if (STAGE < 3) {
                int row = sbase + wb + t * 16 + r;
                *(float2*)(yout + (size_t)row * 64 + n * 8 + c2) = make_float2(d0, d1);
                *(float2*)(yout + (size_t)(row + 8) * 64 + n * 8 + c2) = make_float2(d2, d3);
            }
            ps0 += d0 + d2; ps1 += d1 + d3;
            pq0 += d0 * d0 + d2 * d2; pq1 += d1 * d1 + d3 * d3;
            if (STAGE == 3) {
                mx0 = fmaxf(d0, d2); mx1 = fmaxf(d1, d3);
                mn0 = fminf(d0, d2); mn1 = fminf(d1, d3);
            }
        }
#pragma unroll
        for (int off = 4; off <= 16; off <<= 1) {
            ps0 += __shfl_xor_sync(FULLM, ps0, off);
            ps1 += __shfl_xor_sync(FULLM, ps1, off);
            pq0 += __shfl_xor_sync(FULLM, pq0, off);
            pq1 += __shfl_xor_sync(FULLM, pq1, off);
            if (STAGE == 3) {
                mx0 = fmaxf(mx0, __shfl_xor_sync(FULLM, mx0, off));
                mx1 = fmaxf(mx1, __shfl_xor_sync(FULLM, mx1, off));
                mn0 = fminf(mn0, __shfl_xor_sync(FULLM, mn0, off));
                mn1 = fminf(mn1, __shfl_xor_sync(FULLM, mn1, off));
            }
        }
        if (lane < 4) {
            int ch = n * 8 + c2;
            sps[warp * COUT + ch] = ps0;  sps[warp * COUT + ch + 1] = ps1;
            spq[warp * COUT + ch] = pq0;  spq[warp * COUT + ch + 1] = pq1;
            if (STAGE == 3) {
                smx[warp * COUT + ch] = mx0;  smx[warp * COUT + ch + 1] = mx1;
                smn[warp * COUT + ch] = mn0;  smn[warp * COUT + ch + 1] = mn1;
            }
        }
    }
    __syncthreads();
    for (int ch = tid; ch < COUT; ch += 128) {
        float a = sps[ch] + sps[COUT + ch] + sps[2 * COUT + ch] + sps[3 * COUT + ch];
        float q = spq[ch] + spq[COUT + ch] + spq[2 * COUT + ch] + spq[3 * COUT + ch];
        psum[(size_t)ch * 8192 + blk] = a;
        psq [(size_t)ch * 8192 + blk] = q;
    }
    if (STAGE == 3) {
        for (int i = tid; i < 256; i += 128) {
            int h = i >> 7, ch = i & 127;
            int m = (sbase >> 5) + h;
            ymax[(size_t)m * 128 + ch] =
                fmaxf(smx[(2 * h) * 128 + ch], smx[(2 * h + 1) * 128 + ch]);
            ymin[(size_t)m * 128 + ch] =
                fminf(smn[(2 * h) * 128 + ch], smn[(2 * h + 1) * 128 + ch]);
        }
    }
}

// ---------------- BN finalize ----------------------------------------------
__global__ void bn_finalize(const float* __restrict__ psum, const float* __restrict__ psq,
                            const float* __restrict__ g, const float* __restrict__ beta,
                            float* __restrict__ aff, int NB)
{
    int ch = blockIdx.x, tid = threadIdx.x;
    __shared__ float s1[256], s2[256];
    float a = 0.f, q = 0.f;
    for (int i = tid; i < NB; i += 256) {
        a += psum[(size_t)ch * 8192 + i];
        q += psq [(size_t)ch * 8192 + i];
    }
    s1[tid] = a; s2[tid] = q; __syncthreads();
    for (int st = 128; st > 0; st >>= 1) {
        if (tid < st) { s1[tid] += s1[tid + st]; s2[tid] += s2[tid + st]; }
        __syncthreads();
    }
    if (tid == 0) {
        const float invS = 1.0f / (float)S_TOTAL;
        float mu = s1[0] * invS;
        float var = s2[0] * invS - mu * mu;
        float rs = rsqrtf(var + 1e-5f);
        float aa = g[ch] * rs;
        aff[ch] = aa;
        aff[128 + ch] = beta[ch] - mu * aa;
    }
}

// ---------------- final: affine3 + relu on k-extremum, transpose -----------
__global__ __launch_bounds__(256) void final_kernel(const float* __restrict__ ymax,
                                                    const float* __restrict__ ymin,
                                                    const float* __restrict__ aff,
                                                    float* __restrict__ out)
{
    __shared__ float t[128 * 65];
    int b = blockIdx.x >> 4;
    int mg = blockIdx.x & 15;
    int tid = threadIdx.x;
    for (int i = tid; i < 8192; i += 256) {
        int m = i >> 7, ch = i & 127;
        float a = aff[ch], cc = aff[128 + ch];
        size_t base = ((size_t)(b * MQ + mg * 64 + m)) * 128 + ch;
        float val = (a > 0.f) ? ymax[base] : ymin[base];
        t[ch * 65 + m] = fmaxf(0.f, fmaf(a, val, cc));
    }
    __syncthreads();
    for (int i = tid; i < 8192; i += 256) {
        int ch = i >> 6, m = i & 63;
        out[((size_t)(b * 128 + ch)) * MQ + mg * 64 + m] = t[ch * 65 + m];
    }
}

// ---------------- launch ----------------------------------------------------
extern "C" void kernel_launch(void* const* d_in, const int* in_sizes, int n_in,
                              void* d_out, int out_size)
{
    const float* loc    = (const float*)d_in[0];
    const float* newloc = (const float*)d_in[1];
    const float* feats  = (const float*)d_in[2];
    const float* W1 = (const float*)d_in[3];
    const float* g1 = (const float*)d_in[4];
    const float* b1 = (const float*)d_in[5];
    const float* W2 = (const float*)d_in[6];
    const float* g2 = (const float*)d_in[7];
    const float* b2 = (const float*)d_in[8];
    const float* W3 = (const float*)d_in[9];
    const float* g3 = (const float*)d_in[10];
    const float* b3 = (const float*)d_in[11];
    float* out = (float*)d_out;

    int*   idx   = nullptr;  cudaGetSymbolAddress((void**)&idx,   g_idx);
    float* featT = nullptr;  cudaGetSymbolAddress((void**)&featT, g_featT);
    float* y1    = nullptr;  cudaGetSymbolAddress((void**)&y1,    g_y1);
    float* y2    = nullptr;  cudaGetSymbolAddress((void**)&y2,    g_y2);
    float* ymax  = nullptr;  cudaGetSymbolAddress((void**)&ymax,  g_ymax);
    float* ymin  = nullptr;  cudaGetSymbolAddress((void**)&ymin,  g_ymin);
    float* psum  = nullptr;  cudaGetSymbolAddress((void**)&psum,  g_psum);
    float* psq   = nullptr;  cudaGetSymbolAddress((void**)&psq,   g_psq);
    float* aff   = nullptr;  cudaGetSymbolAddress((void**)&aff,   g_aff);

    const int SM12 = 2 * (64 * 144)  + (128 + 256 + 16 * 64)  * 4;   // 24064
    const int SM3  = 2 * (128 * 144) + (128 + 256 + 16 * 128) * 4;   // 46592
    cudaFuncSetAttribute(knnT_kernel, cudaFuncAttributeMaxDynamicSharedMemorySize, 49152);

    knnT_kernel<<<512, 256, 49152>>>(loc, newloc, feats, featT, idx);

    gemm_mma<1><<<4096, 128, SM12>>>(W1, nullptr, nullptr, y1, nullptr, nullptr,
                                     psum, psq, idx, loc, newloc, featT);
    bn_finalize<<<64, 256>>>(psum, psq, g1, b1, aff + 0 * 256, 4096);

    gemm_mma<2><<<4096, 128, SM12>>>(W2, y1, aff + 0 * 256, y2, nullptr, nullptr,
                                     psum, psq, idx, loc, newloc, featT);
    bn_finalize<<<64, 256>>>(psum, psq, g2, b2, aff + 1 * 256, 4096);

    gemm_mma<3><<<8192, 128, SM3>>>(W3, y2, aff + 1 * 256, nullptr, ymax, ymin,
                                    psum, psq, idx, loc, newloc, featT);
    bn_finalize<<<128, 256>>>(psum, psq, g3, b3, aff + 2 * 256, 8192);

    final_kernel<<<BB * 16, 256>>>(ymax, ymin, aff + 2 * 256, out);
    (void)in_sizes; (void)n_in; (void)out_size;
}

// round 16
// speedup vs baseline: 1.9572x; 1.1461x over previous
#include <cuda_runtime.h>
#include <cuda_bf16.h>
#include <cstdint>

#define BB    16
#define NPTS  4096
#define MQ    1024
#define KNB   32
#define S_TOTAL (BB*MQ*KNB)
#define FULLM 0xffffffffu

typedef unsigned long long ull;

// ---------------- device scratch -------------------------------------------
__device__ __align__(16) int   g_idx[S_TOTAL];
__device__ __align__(16) float g_featT[BB*NPTS*64];
__device__ __align__(16) float g_y1[(size_t)S_TOTAL*64];
__device__ __align__(16) float g_y2[(size_t)S_TOTAL*64];
__device__ __align__(16) float g_ymax[BB*MQ*128];
__device__ __align__(16) float g_ymin[BB*MQ*128];
__device__ __align__(16) float g_psum[128*8192];
__device__ __align__(16) float g_psq [128*8192];
__device__ __align__(16) float g_aff[3][256];

// ---------------- mma helpers ----------------------------------------------
__device__ __forceinline__ void ldm4(uint32_t* r, uint32_t addr) {
    asm volatile("ldmatrix.sync.aligned.m8n8.x4.shared.b16 {%0,%1,%2,%3}, [%4];"
        : "=r"(r[0]), "=r"(r[1]), "=r"(r[2]), "=r"(r[3]) : "r"(addr));
}
__device__ __forceinline__ void mma_bf16(float* d, const uint32_t* a,
                                         uint32_t b0, uint32_t b1) {
    asm volatile("mma.sync.aligned.m16n8k16.row.col.f32.bf16.bf16.f32 "
        "{%0,%1,%2,%3}, {%4,%5,%6,%7}, {%8,%9}, {%0,%1,%2,%3};"
        : "+f"(d[0]), "+f"(d[1]), "+f"(d[2]), "+f"(d[3])
        : "r"(a[0]), "r"(a[1]), "r"(a[2]), "r"(a[3]), "r"(b0), "r"(b1));
}
__device__ __forceinline__ void mk2(float x, float y, uint32_t& h, uint32_t& l) {
    __nv_bfloat162 hh = __floats2bfloat162_rn(x, y);
    h = *(uint32_t*)&hh;
    __nv_bfloat162 ll = __floats2bfloat162_rn(x - __low2float(hh), y - __high2float(hh));
    l = *(uint32_t*)&ll;
}

// ---------------- KNN + features transpose fused ---------------------------
// 256 blocks x 512 threads; 64KB smem: AoS float4 (x,y,z,|p|^2).
// Exact top-32 select: lane top-2 -> pair bitonic sort/merge -> rescan misses.
__global__ __launch_bounds__(512) void knnT_kernel(const float* __restrict__ loc,
                                                   const float* __restrict__ newloc,
                                                   const float* __restrict__ feats,
                                                   float* __restrict__ featT,
                                                   int* __restrict__ idxout)
{
    extern __shared__ __align__(16) char smc[];
    float*  smem  = (float*)smc;
    float4* sloc4 = (float4*)smc;
    int b = blockIdx.x >> 4;
    int grp = blockIdx.x & 15;
    int tid = threadIdx.x;

    // transpose this block's 256-n slice (two 128-row halves)
    for (int h = 0; h < 2; h++) {
        int n0 = grp * 256 + h * 128;
        for (int i = tid; i < 64 * 128; i += 512) {
            int c = i >> 7, n = i & 127;
            smem[n * 65 + c] = feats[((size_t)b * 64 + c) * NPTS + n0 + n];
        }
        __syncthreads();
        for (int i = tid; i < 64 * 128; i += 512) {
            int n = i >> 6, c = i & 63;
            featT[((size_t)b * NPTS + n0 + n) * 64 + c] = smem[n * 65 + c];
        }
        __syncthreads();
    }

    // AoS loc + precomputed squared norm
    for (int i = tid; i < NPTS; i += 512) {
        const float* p = loc + ((size_t)b * NPTS + i) * 3;
        float x = p[0], y = p[1], z = p[2];
        sloc4[i] = make_float4(x, y, z, x * x + y * y + z * z);
    }
    __syncthreads();

    int warp = tid >> 5, lane = tid & 31;
    for (int j = 0; j < 4; j++) {
        int m = grp * 64 + j * 16 + warp;
        const float* q = newloc + ((size_t)b * MQ + m) * 3;
        float qx = q[0], qy = q[1], qz = q[2];
        float q2 = qx * qx + qy * qy + qz * qz;

        // phase 1: lane-local top-2 (strict < in scan order == (d2,idx) lex)
        float v1 = 3.4e38f, v2 = 3.4e38f;
        int   i1 = -1, i2 = -1;
#pragma unroll 4
        for (int it = 0; it < 128; it++) {
            int p = it * 32 + lane;
            float4 P = sloc4[p];
            float dot = qx * P.x + qy * P.y + qz * P.z;
            float d2 = (q2 + P.w) - 2.0f * dot;
            if (d2 < v2) {
                if (d2 < v1) { v2 = v1; i2 = i1; v1 = d2; i1 = p; }
                else         { v2 = d2; i2 = p; }
            }
        }

        // phase 2: pair bitonic sort of both arrays, lowest-32 merge
        float va = v1, vb = v2; int ia = i1, ib = i2;
#pragma unroll
        for (int k = 2; k <= 32; k <<= 1) {
#pragma unroll
            for (int jj = k >> 1; jj; jj >>= 1) {
                bool keep = ((lane & jj) == 0) == ((lane & k) == 0);
                float ov = __shfl_xor_sync(FULLM, va, jj);
                int   oi = __shfl_xor_sync(FULLM, ia, jj);
                bool lt = (va < ov) || (va == ov && ia < oi);
                bool sel = (keep == lt);
                va = sel ? va : ov;  ia = sel ? ia : oi;
                float ow = __shfl_xor_sync(FULLM, vb, jj);
                int   oj = __shfl_xor_sync(FULLM, ib, jj);
                bool lt2 = (vb < ow) || (vb == ow && ib < oj);
                bool sel2 = (keep == lt2);
                vb = sel2 ? vb : ow;  ib = sel2 ? ib : oj;
            }
        }
        float brv = __shfl_sync(FULLM, vb, 31 - lane);
        int   bri = __shfl_sync(FULLM, ib, 31 - lane);
        bool ltab = (va < brv) || (va == brv && ia < bri);
        float Cf = ltab ? va : brv;
        int   Ci = ltab ? ia : bri;
#pragma unroll
        for (int jj = 16; jj; jj >>= 1) {
            bool lower = (lane & jj) == 0;
            float ov = __shfl_xor_sync(FULLM, Cf, jj);
            int   oi = __shfl_xor_sync(FULLM, Ci, jj);
            bool lt = (Cf < ov) || (Cf == ov && Ci < oi);
            bool sel = (lower == lt);
            Cf = sel ? Cf : ov;  Ci = sel ? Ci : oi;
        }
        float Tpd = __shfl_sync(FULLM, Cf, 31);
        int   Tpi = __shfl_sync(FULLM, Ci, 31);

        // phase 3: rescan for lane-rank>=3 candidates inside the bound
#pragma unroll 4
        for (int it = 0; it < 128; it++) {
            int p = it * 32 + lane;
            float4 P = sloc4[p];
            float dot = qx * P.x + qy * P.y + qz * P.z;
            float d2 = (q2 + P.w) - 2.0f * dot;
            bool inb = (d2 < Tpd) || (d2 == Tpd && p < Tpi);
            bool miss = inb && (p != i1) && (p != i2);
            unsigned bm = __ballot_sync(FULLM, miss);
            while (bm) {
                int src = __ffs(bm) - 1; bm &= bm - 1;
                float nf = __shfl_sync(FULLM, d2, src);
                int   ni = it * 32 + src;
                int pos = __popc(__ballot_sync(FULLM, (Cf < nf) || (Cf == nf && Ci < ni)));
                float pf = __shfl_up_sync(FULLM, Cf, 1);
                int   pi = __shfl_up_sync(FULLM, Ci, 1);
                if (lane == pos)      { Cf = nf; Ci = ni; }
                else if (lane > pos)  { Cf = pf; Ci = pi; }
            }
        }
        idxout[((size_t)b * MQ + m) * KNB + lane] = Ci;
    }
}

// ---------------- tensor-core GEMM stage, register-direct A ----------------
template<int STAGE>
__global__ __launch_bounds__(128, 4) void gemm_mma(
    const float* __restrict__ W, const float* __restrict__ src,
    const float* __restrict__ aff, float* __restrict__ yout,
    float* __restrict__ ymax, float* __restrict__ ymin,
    float* __restrict__ psum, float* __restrict__ psq,
    const int* __restrict__ idx, const float* __restrict__ loc,
    const float* __restrict__ newloc, const float* __restrict__ featT)
{
    constexpr int COUT = (STAGE == 3) ? 128 : 64;
    constexpr int SPB  = (STAGE == 3) ? 64 : 128;
    constexpr int NT   = COUT / 8;
    constexpr int MT   = SPB / 64;
    constexpr int WBYT = COUT * 72 * 2;

    extern __shared__ __align__(16) char smg[];
    __nv_bfloat16* Wh = (__nv_bfloat16*)smg;
    __nv_bfloat16* Wl = (__nv_bfloat16*)(smg + WBYT);
    float* afs  = (float*)(smg + 2 * WBYT);
    float* wloc = afs + 128;
    float* sps  = wloc + 256;
    float* spq  = sps + 4 * COUT;
    float* smx  = spq + 4 * COUT;
    float* smn  = smx + 4 * COUT;

    int tid = threadIdx.x, warp = tid >> 5, lane = tid & 31;
    int blk = blockIdx.x;
    int sbase = blk * SPB;
    int r = lane >> 2, cg = lane & 3, c2 = cg * 2;
    int wb = warp * (MT * 16);

    if (STAGE > 1)
        afs[tid] = (tid < 64) ? aff[tid] : aff[128 + tid - 64];

    for (int i = tid; i < COUT * 64; i += 128) {
        int co = i >> 6, k = i & 63;
        float v = (STAGE == 1) ? W[co * 67 + 3 + k] : W[co * 64 + k];
        __nv_bfloat16 h = __float2bfloat16(v);
        Wh[co * 72 + k] = h;
        Wl[co * 72 + k] = __float2bfloat16(v - __bfloat162float(h));
    }
    if (STAGE == 1)
        for (int i = tid; i < 192; i += 128) {
            int co = i / 3, c = i - co * 3;
            wloc[co * 4 + c] = W[co * 67 + c];
        }
    __syncthreads();

    const float* row0[MT];
    const float* row1[MT];
    float acc[MT][NT][4];
#pragma unroll
    for (int t = 0; t < MT; t++) {
        int s0 = sbase + wb + t * 16 + r;
        int s1 = s0 + 8;
        if (STAGE == 1) {
            int n0 = idx[s0], n1 = idx[s1];
            int b = s0 >> 15;
            row0[t] = featT + (size_t)(b * NPTS + n0) * 64;
            row1[t] = featT + (size_t)(b * NPTS + n1) * 64;
            const float* lp0 = loc + (size_t)(b * NPTS + n0) * 3;
            const float* lp1 = loc + (size_t)(b * NPTS + n1) * 3;
            const float* qp0 = newloc + (size_t)(b * MQ + ((s0 >> 5) & (MQ - 1))) * 3;
            const float* qp1 = newloc + (size_t)(b * MQ + ((s1 >> 5) & (MQ - 1))) * 3;
            float rx0 = lp0[0] - qp0[0], ry0 = lp0[1] - qp0[1], rz0 = lp0[2] - qp0[2];
            float rx1 = lp1[0] - qp1[0], ry1 = lp1[1] - qp1[1], rz1 = lp1[2] - qp1[2];
#pragma unroll
            for (int n = 0; n < NT; n++)
#pragma unroll
                for (int cc = 0; cc < 2; cc++) {
                    const float* wl = wloc + (n * 8 + c2 + cc) * 4;
                    acc[t][n][cc]     = rx0 * wl[0] + ry0 * wl[1] + rz0 * wl[2];
                    acc[t][n][2 + cc] = rx1 * wl[0] + ry1 * wl[1] + rz1 * wl[2];
                }
        } else {
            row0[t] = src + (size_t)s0 * 64;
            row1[t] = src + (size_t)s1 * 64;
#pragma unroll
            for (int n = 0; n < NT; n++)
#pragma unroll
                for (int p = 0; p < 4; p++) acc[t][n][p] = 0.f;
        }
    }

    uint32_t aWh = (uint32_t)__cvta_generic_to_shared(Wh);
    uint32_t aWl = (uint32_t)__cvta_generic_to_shared(Wl);

#pragma unroll
    for (int k = 0; k < 4; k++) {
        int c0 = c2 + k * 16;
        uint32_t ah[MT][4], al[MT][4];
#pragma unroll
        for (int t = 0; t < MT; t++) {
            float2 u00 = *(const float2*)(row0[t] + c0);
            float2 u08 = *(const float2*)(row0[t] + c0 + 8);
            float2 u10 = *(const float2*)(row1[t] + c0);
            float2 u18 = *(const float2*)(row1[t] + c0 + 8);
            if (STAGE > 1) {
                float2 a0 = *(const float2*)(afs + c0);
                float2 cc0 = *(const float2*)(afs + 64 + c0);
                float2 a8 = *(const float2*)(afs + c0 + 8);
                float2 cc8 = *(const float2*)(afs + 64 + c0 + 8);
                u00.x = fmaxf(0.f, fmaf(a0.x, u00.x, cc0.x));
                u00.y = fmaxf(0.f, fmaf(a0.y, u00.y, cc0.y));
                u08.x = fmaxf(0.f, fmaf(a8.x, u08.x, cc8.x));
                u08.y = fmaxf(0.f, fmaf(a8.y, u08.y, cc8.y));
                u10.x = fmaxf(0.f, fmaf(a0.x, u10.x, cc0.x));
                u10.y = fmaxf(0.f, fmaf(a0.y, u10.y, cc0.y));
                u18.x = fmaxf(0.f, fmaf(a8.x, u18.x, cc8.x));
                u18.y = fmaxf(0.f, fmaf(a8.y, u18.y, cc8.y));
            }
            mk2(u00.x, u00.y, ah[t][0], al[t][0]);
            mk2(u10.x, u10.y, ah[t][1], al[t][1]);
            mk2(u08.x, u08.y, ah[t][2], al[t][2]);
            mk2(u18.x, u18.y, ah[t][3], al[t][3]);
        }
#pragma unroll
        for (int p = 0; p < NT / 2; p++) {
            uint32_t bo = (p * 16 + (lane & 7) + ((lane >> 4) & 1) * 8) * 144
                        + k * 32 + ((lane >> 3) & 1) * 16;
            uint32_t bh[4], bl[4];
            ldm4(bh, aWh + bo);
            ldm4(bl, aWl + bo);
#pragma unroll
            for (int t = 0; t < MT; t++) {
                mma_bf16(acc[t][2 * p],     ah[t], bh[0], bh[1]);
                mma_bf16(acc[t][2 * p],     ah[t], bl[0], bl[1]);
                mma_bf16(acc[t][2 * p],     al[t], bh[0], bh[1]);
                mma_bf16(acc[t][2 * p + 1], ah[t], bh[2], bh[3]);
                mma_bf16(acc[t][2 * p + 1], ah[t], bl[2], bl[3]);
                mma_bf16(acc[t][2 * p + 1], al[t], bh[2], bh[3]);
            }
        }
    }

#pragma unroll
    for (int n = 0; n < NT; n++) {
        float ps0 = 0.f, ps1 = 0.f, pq0 = 0.f, pq1 = 0.f;
        float mx0 = -3.4e38f, mx1 = -3.4e38f, mn0 = 3.4e38f, mn1 = 3.4e38f;
#pragma unroll
        for (int t = 0; t < MT; t++) {
            float d0 = acc[t][n][0], d1 = acc[t][n][1];
            float d2 = acc[t][n][2], d3 = acc[t][n][3];
            if (STAGE < 3) {
                int row = sbase + wb + t * 16 + r;
                *(float2*)(yout + (size_t)row * 64 + n * 8 + c2) = make_float2(d0, d1);
                *(float2*)(yout + (size_t)(row + 8) * 64 + n * 8 + c2) = make_float2(d2, d3);
            }
            ps0 += d0 + d2; ps1 += d1 + d3;
            pq0 += d0 * d0 + d2 * d2; pq1 += d1 * d1 + d3 * d3;
            if (STAGE == 3) {
                mx0 = fmaxf(d0, d2); mx1 = fmaxf(d1, d3);
                mn0 = fminf(d0, d2); mn1 = fminf(d1, d3);
            }
        }
#pragma unroll
        for (int off = 4; off <= 16; off <<= 1) {
            ps0 += __shfl_xor_sync(FULLM, ps0, off);
            ps1 += __shfl_xor_sync(FULLM, ps1, off);
            pq0 += __shfl_xor_sync(FULLM, pq0, off);
            pq1 += __shfl_xor_sync(FULLM, pq1, off);
            if (STAGE == 3) {
                mx0 = fmaxf(mx0, __shfl_xor_sync(FULLM, mx0, off));
                mx1 = fmaxf(mx1, __shfl_xor_sync(FULLM, mx1, off));
                mn0 = fminf(mn0, __shfl_xor_sync(FULLM, mn0, off));
                mn1 = fminf(mn1, __shfl_xor_sync(FULLM, mn1, off));
            }
        }
        if (lane < 4) {
            int ch = n * 8 + c2;
            sps[warp * COUT + ch] = ps0;  sps[warp * COUT + ch + 1] = ps1;
            spq[warp * COUT + ch] = pq0;  spq[warp * COUT + ch + 1] = pq1;
            if (STAGE == 3) {
                smx[warp * COUT + ch] = mx0;  smx[warp * COUT + ch + 1] = mx1;
                smn[warp * COUT + ch] = mn0;  smn[warp * COUT + ch + 1] = mn1;
            }
        }
    }
    __syncthreads();
    for (int ch = tid; ch < COUT; ch += 128) {
        float a = sps[ch] + sps[COUT + ch] + sps[2 * COUT + ch] + sps[3 * COUT + ch];
        float q = spq[ch] + spq[COUT + ch] + spq[2 * COUT + ch] + spq[3 * COUT + ch];
        psum[(size_t)ch * 8192 + blk] = a;
        psq [(size_t)ch * 8192 + blk] = q;
    }
    if (STAGE == 3) {
        for (int i = tid; i < 256; i += 128) {
            int h = i >> 7, ch = i & 127;
            int m = (sbase >> 5) + h;
            ymax[(size_t)m * 128 + ch] =
                fmaxf(smx[(2 * h) * 128 + ch], smx[(2 * h + 1) * 128 + ch]);
            ymin[(size_t)m * 128 + ch] =
                fminf(smn[(2 * h) * 128 + ch], smn[(2 * h + 1) * 128 + ch]);
        }
    }
}

// ---------------- BN finalize ----------------------------------------------
__global__ void bn_finalize(const float* __restrict__ psum, const float* __restrict__ psq,
                            const float* __restrict__ g, const float* __restrict__ beta,
                            float* __restrict__ aff, int NB)
{
    int ch = blockIdx.x, tid = threadIdx.x;
    __shared__ float s1[256], s2[256];
    float a = 0.f, q = 0.f;
    for (int i = tid; i < NB; i += 256) {
        a += psum[(size_t)ch * 8192 + i];
        q += psq [(size_t)ch * 8192 + i];
    }
    s1[tid] = a; s2[tid] = q; __syncthreads();
    for (int st = 128; st > 0; st >>= 1) {
        if (tid < st) { s1[tid] += s1[tid + st]; s2[tid] += s2[tid + st]; }
        __syncthreads();
    }
    if (tid == 0) {
        const float invS = 1.0f / (float)S_TOTAL;
        float mu = s1[0] * invS;
        float var = s2[0] * invS - mu * mu;
        float rs = rsqrtf(var + 1e-5f);
        float aa = g[ch] * rs;
        aff[ch] = aa;
        aff[128 + ch] = beta[ch] - mu * aa;
    }
}

// ---------------- final: affine3 + relu on k-extremum, transpose -----------
__global__ __launch_bounds__(256) void final_kernel(const float* __restrict__ ymax,
                                                    const float* __restrict__ ymin,
                                                    const float* __restrict__ aff,
                                                    float* __restrict__ out)
{
    __shared__ float t[128 * 65];
    int b = blockIdx.x >> 4;
    int mg = blockIdx.x & 15;
    int tid = threadIdx.x;
    for (int i = tid; i < 8192; i += 256) {
        int m = i >> 7, ch = i & 127;
        float a = aff[ch], cc = aff[128 + ch];
        size_t base = ((size_t)(b * MQ + mg * 64 + m)) * 128 + ch;
        float val = (a > 0.f) ? ymax[base] : ymin[base];
        t[ch * 65 + m] = fmaxf(0.f, fmaf(a, val, cc));
    }
    __syncthreads();
    for (int i = tid; i < 8192; i += 256) {
        int ch = i >> 6, m = i & 63;
        out[((size_t)(b * 128 + ch)) * MQ + mg * 64 + m] = t[ch * 65 + m];
    }
}

// ---------------- launch ----------------------------------------------------
extern "C" void kernel_launch(void* const* d_in, const int* in_sizes, int n_in,
                              void* d_out, int out_size)
{
    const float* loc    = (const float*)d_in[0];
    const float* newloc = (const float*)d_in[1];
    const float* feats  = (const float*)d_in[2];
    const float* W1 = (const float*)d_in[3];
    const float* g1 = (const float*)d_in[4];
    const float* b1 = (const float*)d_in[5];
    const float* W2 = (const float*)d_in[6];
    const float* g2 = (const float*)d_in[7];
    const float* b2 = (const float*)d_in[8];
    const float* W3 = (const float*)d_in[9];
    const float* g3 = (const float*)d_in[10];
    const float* b3 = (const float*)d_in[11];
    float* out = (float*)d_out;

    int*   idx   = nullptr;  cudaGetSymbolAddress((void**)&idx,   g_idx);
    float* featT = nullptr;  cudaGetSymbolAddress((void**)&featT, g_featT);
    float* y1    = nullptr;  cudaGetSymbolAddress((void**)&y1,    g_y1);
    float* y2    = nullptr;  cudaGetSymbolAddress((void**)&y2,    g_y2);
    float* ymax  = nullptr;  cudaGetSymbolAddress((void**)&ymax,  g_ymax);
    float* ymin  = nullptr;  cudaGetSymbolAddress((void**)&ymin,  g_ymin);
    float* psum  = nullptr;  cudaGetSymbolAddress((void**)&psum,  g_psum);
    float* psq   = nullptr;  cudaGetSymbolAddress((void**)&psq,   g_psq);
    float* aff   = nullptr;  cudaGetSymbolAddress((void**)&aff,   g_aff);

    const int SM12 = 2 * (64 * 144)  + (128 + 256 + 16 * 64)  * 4;   // 24064
    const int SM3  = 2 * (128 * 144) + (128 + 256 + 16 * 128) * 4;   // 46592
    cudaFuncSetAttribute(knnT_kernel, cudaFuncAttributeMaxDynamicSharedMemorySize, 65536);

    knnT_kernel<<<256, 512, 65536>>>(loc, newloc, feats, featT, idx);

    gemm_mma<1><<<4096, 128, SM12>>>(W1, nullptr, nullptr, y1, nullptr, nullptr,
                                     psum, psq, idx, loc, newloc, featT);
    bn_finalize<<<64, 256>>>(psum, psq, g1, b1, aff + 0 * 256, 4096);

    gemm_mma<2><<<4096, 128, SM12>>>(W2, y1, aff + 0 * 256, y2, nullptr, nullptr,
                                     psum, psq, idx, loc, newloc, featT);
    bn_finalize<<<64, 256>>>(psum, psq, g2, b2, aff + 1 * 256, 4096);

    gemm_mma<3><<<8192, 128, SM3>>>(W3, y2, aff + 1 * 256, nullptr, ymax, ymin,
                                    psum, psq, idx, loc, newloc, featT);
    bn_finalize<<<128, 256>>>(psum, psq, g3, b3, aff + 2 * 256, 8192);

    final_kernel<<<BB * 16, 256>>>(ymax, ymin, aff + 2 * 256, out);
    (void)in_sizes; (void)n_in; (void)out_size;
}